// round 3
// baseline (speedup 1.0000x reference)
#include <cuda_runtime.h>

// ---------------------------------------------------------------------------
// Problem constants
// ---------------------------------------------------------------------------
constexpr int Nu = 50000, Np = 20000, IN = 256, EF = 64, H = 128;
constexpr int Ep = 200000, Ec = 800000, Eu = 300000;
constexpr int HH = H * H;

// ---------------------------------------------------------------------------
// Scratch (device global; allocation-free contract)
// ---------------------------------------------------------------------------
struct alignas(16) Scratch {
    float h_user[(size_t)Nu * H];
    float init_user[(size_t)Nu * H];
    float ctx[(size_t)Nu * H];
    float user_new[(size_t)Nu * H];   // also reused as classifier tmp
    float agg_ucu[(size_t)Nu * H];
    float h_post[(size_t)Np * H];
    float init_post[(size_t)Np * H];
    float post_enc[(size_t)Np * H];
    float post_new[(size_t)Np * H];
    float agg_pub[(size_t)Np * H];
    float agg_com[(size_t)Np * H];
    int cnt_pub_u[Nu]; int cnt_com_u[Nu]; int cnt_ucu_u[Nu]; int cnt_ucu_v[Nu];
    int cnt_pub_v[Np]; int cnt_com_v[Np];
    float inv_pub_u[Nu]; float inv_com_u[Nu]; float inv_ucu_v[Nu];
    float inv_pub_v[Np]; float inv_com_v[Np];
    int deg_user[Nu]; int deg_post[Np];
    float avgpost[IN];
    float cvec[H];
    float Wsum[2 * HH]; float bsum[2 * H];
    float gm_user[H]; float gm_post[H];   // contiguous: single memset
    int nz[2];
};
__device__ Scratch gS;

// ---------------------------------------------------------------------------
// Helpers
// ---------------------------------------------------------------------------
__device__ __forceinline__ float warp_sum(float v) {
#pragma unroll
    for (int o = 16; o; o >>= 1) v += __shfl_xor_sync(0xffffffffu, v, o);
    return v;
}

__device__ __forceinline__ void red4(float* p, float4 v) {
    asm volatile("red.global.add.v4.f32 [%0], {%1,%2,%3,%4};"
                 :: "l"(p), "f"(v.x), "f"(v.y), "f"(v.z), "f"(v.w) : "memory");
}

__device__ __forceinline__ float lrelu(float x) { return x >= 0.f ? x : 0.01f * x; }

// ---------------------------------------------------------------------------
// Generic fp32 GEMM:  C[M,128] (=/+)= act(A[M,K] @ W[K,128] + bias)
// BM=64, BN=128, BK=16; 256 threads; per-thread 8x4 register tile.
// ROWSCALE: A row r is multiplied by rs[r] at load (folds segment-mean divide).
// ACCUM: C += (acc + bias); else C = act(acc + bias).
// ---------------------------------------------------------------------------
template <int ACT, bool ACCUM, bool ROWSCALE>
__global__ void gemm128(const float* __restrict__ A, const float* __restrict__ W,
                        const float* __restrict__ bias, const float* __restrict__ rs,
                        float* __restrict__ Cb, int M, int K) {
    __shared__ float As[16][64];
    __shared__ float Ws[16][128];
    const int tid = threadIdx.x;
    const int ty = tid >> 5, tx = tid & 31;
    const int rowBase = blockIdx.x * 64;

    float acc[8][4];
#pragma unroll
    for (int r = 0; r < 8; r++)
#pragma unroll
        for (int c = 0; c < 4; c++) acc[r][c] = 0.f;

    const int arow = tid >> 2;
    const int ak = (tid & 3) * 4;
    int grow = rowBase + arow; if (grow > M - 1) grow = M - 1;
    const float scale = ROWSCALE ? rs[grow] : 1.f;

    for (int k0 = 0; k0 < K; k0 += 16) {
        float4 av = *(const float4*)&A[(size_t)grow * K + k0 + ak];
        As[ak + 0][arow] = av.x * scale;
        As[ak + 1][arow] = av.y * scale;
        As[ak + 2][arow] = av.z * scale;
        As[ak + 3][arow] = av.w * scale;
#pragma unroll
        for (int t = 0; t < 2; t++) {
            int idx = tid + t * 256;
            int wk = idx >> 5, wc = (idx & 31) * 4;
            *(float4*)&Ws[wk][wc] = *(const float4*)&W[(size_t)(k0 + wk) * 128 + wc];
        }
        __syncthreads();
#pragma unroll
        for (int kk = 0; kk < 16; kk++) {
            float4 a0 = *(const float4*)&As[kk][ty * 8];
            float4 a1 = *(const float4*)&As[kk][ty * 8 + 4];
            float4 b  = *(const float4*)&Ws[kk][tx * 4];
            float ar[8] = {a0.x, a0.y, a0.z, a0.w, a1.x, a1.y, a1.z, a1.w};
#pragma unroll
            for (int r = 0; r < 8; r++) {
                acc[r][0] += ar[r] * b.x;
                acc[r][1] += ar[r] * b.y;
                acc[r][2] += ar[r] * b.z;
                acc[r][3] += ar[r] * b.w;
            }
        }
        __syncthreads();
    }

    float4 bv = *(const float4*)&bias[tx * 4];
#pragma unroll
    for (int r = 0; r < 8; r++) {
        int row = rowBase + ty * 8 + r;
        if (row < M) {
            float4 o;
            o.x = acc[r][0] + bv.x; o.y = acc[r][1] + bv.y;
            o.z = acc[r][2] + bv.z; o.w = acc[r][3] + bv.w;
            float4* cp = (float4*)&Cb[(size_t)row * 128 + tx * 4];
            if (ACCUM) {
                float4 ci = *cp;
                o.x += ci.x; o.y += ci.y; o.z += ci.z; o.w += ci.w;
            }
            if (ACT == 1) { o.x = lrelu(o.x); o.y = lrelu(o.y); o.z = lrelu(o.z); o.w = lrelu(o.w); }
            if (ACT == 2) { o.x = fmaxf(o.x, 0.f); o.y = fmaxf(o.y, 0.f); o.z = fmaxf(o.z, 0.f); o.w = fmaxf(o.w, 0.f); }
            *cp = o;
        }
    }
}

// ---------------------------------------------------------------------------
// Fused conversation-context kernel:
//   per edge e: cc = relu(LN(parent_feat[e] @ conv_W[:64] + cvec)); ctx[ucu_u[e]] += cc
// Same GEMM structure (K=64); each warp owns 8 full rows -> warp-level LN.
// ---------------------------------------------------------------------------
__global__ void conv_kernel(const float* __restrict__ A, const float* __restrict__ W,
                            const float* __restrict__ cvec,
                            const float* __restrict__ gw, const float* __restrict__ be,
                            const int* __restrict__ uidx, float* __restrict__ ctx, int M) {
    __shared__ float As[16][64];
    __shared__ float Ws[16][128];
    const int tid = threadIdx.x;
    const int ty = tid >> 5, tx = tid & 31;
    const int rowBase = blockIdx.x * 64;

    float acc[8][4];
#pragma unroll
    for (int r = 0; r < 8; r++)
#pragma unroll
        for (int c = 0; c < 4; c++) acc[r][c] = 0.f;

    const int arow = tid >> 2;
    const int ak = (tid & 3) * 4;
    int grow = rowBase + arow; if (grow > M - 1) grow = M - 1;

    for (int k0 = 0; k0 < 64; k0 += 16) {
        float4 av = *(const float4*)&A[(size_t)grow * 64 + k0 + ak];
        As[ak + 0][arow] = av.x;
        As[ak + 1][arow] = av.y;
        As[ak + 2][arow] = av.z;
        As[ak + 3][arow] = av.w;
#pragma unroll
        for (int t = 0; t < 2; t++) {
            int idx = tid + t * 256;
            int wk = idx >> 5, wc = (idx & 31) * 4;
            *(float4*)&Ws[wk][wc] = *(const float4*)&W[(size_t)(k0 + wk) * 128 + wc];
        }
        __syncthreads();
#pragma unroll
        for (int kk = 0; kk < 16; kk++) {
            float4 a0 = *(const float4*)&As[kk][ty * 8];
            float4 a1 = *(const float4*)&As[kk][ty * 8 + 4];
            float4 b  = *(const float4*)&Ws[kk][tx * 4];
            float ar[8] = {a0.x, a0.y, a0.z, a0.w, a1.x, a1.y, a1.z, a1.w};
#pragma unroll
            for (int r = 0; r < 8; r++) {
                acc[r][0] += ar[r] * b.x;
                acc[r][1] += ar[r] * b.y;
                acc[r][2] += ar[r] * b.z;
                acc[r][3] += ar[r] * b.w;
            }
        }
        __syncthreads();
    }

    float4 cv = ((const float4*)cvec)[tx];
    float4 gg = ((const float4*)gw)[tx];
    float4 bb = ((const float4*)be)[tx];
#pragma unroll
    for (int r = 0; r < 8; r++) {
        int row = rowBase + ty * 8 + r;
        float v0 = acc[r][0] + cv.x, v1 = acc[r][1] + cv.y;
        float v2 = acc[r][2] + cv.z, v3 = acc[r][3] + cv.w;
        float s  = warp_sum(v0 + v1 + v2 + v3);
        float ss = warp_sum(v0 * v0 + v1 * v1 + v2 * v2 + v3 * v3);
        float mean = s * (1.f / 128.f);
        float var = ss * (1.f / 128.f) - mean * mean;
        float rr = rsqrtf(var + 1e-5f);
        v0 = fmaxf((v0 - mean) * rr * gg.x + bb.x, 0.f);
        v1 = fmaxf((v1 - mean) * rr * gg.y + bb.y, 0.f);
        v2 = fmaxf((v2 - mean) * rr * gg.z + bb.z, 0.f);
        v3 = fmaxf((v3 - mean) * rr * gg.w + bb.w, 0.f);
        if (row < M) {
            int u = uidx[row];
            red4(&ctx[(size_t)u * 128 + tx * 4], make_float4(v0, v1, v2, v3));
        }
    }
}

// ---------------------------------------------------------------------------
// Small kernels
// ---------------------------------------------------------------------------
__global__ void count_kernel(const int* __restrict__ idx, int n, int* __restrict__ cnt) {
    int i = blockIdx.x * blockDim.x + threadIdx.x;
    if (i < n) atomicAdd(&cnt[idx[i]], 1);
}

__global__ void prep_user_kernel() {
    int i = blockIdx.x * blockDim.x + threadIdx.x;
    int flag = 0;
    if (i < Nu) {
        int a = gS.cnt_pub_u[i], b = gS.cnt_com_u[i];
        int c = gS.cnt_ucu_u[i], d = gS.cnt_ucu_v[i];
        gS.inv_pub_u[i] = 1.f / (float)(a > 1 ? a : 1);
        gS.inv_com_u[i] = 1.f / (float)(b > 1 ? b : 1);
        gS.inv_ucu_v[i] = 1.f / (float)(d > 1 ? d : 1);
        int deg = a + b + c + d;
        gS.deg_user[i] = deg;
        flag = deg > 0;
    }
    unsigned m = __ballot_sync(0xffffffffu, flag);
    if ((threadIdx.x & 31) == 0) atomicAdd(&gS.nz[0], __popc(m));
}

__global__ void prep_post_kernel() {
    int i = blockIdx.x * blockDim.x + threadIdx.x;
    int flag = 0;
    if (i < Np) {
        int a = gS.cnt_pub_v[i], b = gS.cnt_com_v[i];
        gS.inv_pub_v[i] = 1.f / (float)(a > 1 ? a : 1);
        gS.inv_com_v[i] = 1.f / (float)(b > 1 ? b : 1);
        int deg = a + b;
        gS.deg_post[i] = deg;
        flag = deg > 0;
    }
    unsigned m = __ballot_sync(0xffffffffu, flag);
    if ((threadIdx.x & 31) == 0) atomicAdd(&gS.nz[1], __popc(m));
}

__global__ void avgpost_kernel(const float* __restrict__ post_x) {
    int col = threadIdx.x;                 // 256 threads = 256 cols
    float s = 0.f;
    for (int r = blockIdx.x; r < Np; r += gridDim.x)
        s += post_x[(size_t)r * IN + col];
    atomicAdd(&gS.avgpost[col], s);
}

__global__ void cvec_kernel(const float* __restrict__ conv_W, const float* __restrict__ conv_b) {
    int c = threadIdx.x;                   // 128 threads
    float s = conv_b[c];
    const float scale = 1.f / (float)Np;
    for (int k = 0; k < IN; k++)
        s += gS.avgpost[k] * scale * conv_W[(size_t)(EF + k) * H + c];
    gS.cvec[c] = s;
}

__global__ void wsum_kernel(const float* __restrict__ Wself, const float* __restrict__ bself) {
    int i = blockIdx.x * blockDim.x + threadIdx.x;
    if (i < 2 * HH) {
        int l = i / HH, j = i % HH;
        gS.Wsum[i] = Wself[(size_t)(l * 3 + 0) * HH + j] + Wself[(size_t)(l * 3 + 1) * HH + j];
    }
    if (i < 2 * H) {
        int l = i / H, j = i % H;
        gS.bsum[i] = bself[(l * 3 + 0) * H + j] + bself[(l * 3 + 1) * H + j];
    }
}

// ctx[u] += coef * inv_u[u] * post_enc[v]   (one warp per edge)
__global__ void ctx_post_kernel(const int* __restrict__ vv, const int* __restrict__ uu, int n,
                                float coef, const float* __restrict__ invu,
                                const float* __restrict__ post_enc, float* __restrict__ ctx) {
    int e = (blockIdx.x * blockDim.x + threadIdx.x) >> 5;
    int lane = threadIdx.x & 31;
    if (e >= n) return;
    int u = uu[e], v = vv[e];
    float s = coef * invu[u];
    float4 p = ((const float4*)post_enc)[(size_t)v * 32 + lane];
    p.x *= s; p.y *= s; p.z *= s; p.w *= s;
    red4(&ctx[(size_t)u * 128 + lane * 4], p);
}

// agg[dst] += src_feat[src]   (one warp per edge)
__global__ void scatter_kernel(const int* __restrict__ src, const int* __restrict__ dst, int n,
                               const float* __restrict__ sbuf, float* __restrict__ dbuf) {
    int e = (blockIdx.x * blockDim.x + threadIdx.x) >> 5;
    int lane = threadIdx.x & 31;
    if (e >= n) return;
    int s = src[e], d = dst[e];
    float4 v = ((const float4*)sbuf)[(size_t)s * 32 + lane];
    red4(&dbuf[(size_t)d * 128 + lane * 4], v);
}

__global__ void blend_kernel() {
    size_t i = (size_t)blockIdx.x * blockDim.x + threadIdx.x;
    if (i < (size_t)Nu * H)
        gS.h_user[i] = 0.7f * gS.h_user[i] + 0.3f * gS.ctx[i];
}

// Column sums over rows with deg>0
__global__ void colsum_kernel(const float* __restrict__ buf, const int* __restrict__ deg,
                              int Nr, float* __restrict__ gm) {
    __shared__ float s[128];
    if (threadIdx.x < 128) s[threadIdx.x] = 0.f;
    __syncthreads();
    int col = threadIdx.x & 127, sub = threadIdx.x >> 7;
    float local = 0.f;
    for (int r = blockIdx.x * 2 + sub; r < Nr; r += gridDim.x * 2)
        if (deg[r] > 0) local += buf[(size_t)r * 128 + col];
    atomicAdd(&s[col], local);
    __syncthreads();
    if (threadIdx.x < 128) atomicAdd(&gm[threadIdx.x], s[threadIdx.x]);
}

// fix_zero_degree + LayerNorm (+ optional leaky relu). One warp per row.
template <bool LRELU>
__global__ void fix_ln_kernel(const float* __restrict__ hn, const float* __restrict__ init,
                              const int* __restrict__ deg, const float* __restrict__ gm,
                              const int* __restrict__ nzp,
                              const float* __restrict__ g, const float* __restrict__ b,
                              int Nr, float* __restrict__ out) {
    int w = (blockIdx.x * blockDim.x + threadIdx.x) >> 5;
    int lane = threadIdx.x & 31;
    if (w >= Nr) return;
    float4 v;
    if (deg[w] == 0) {
        float nz = fmaxf((float)(*nzp), 1.f);
        float4 e = ((const float4*)init)[(size_t)w * 32 + lane];
        float4 gv = ((const float4*)gm)[lane];
        v.x = 0.9f * e.x + 0.1f * gv.x / nz;
        v.y = 0.9f * e.y + 0.1f * gv.y / nz;
        v.z = 0.9f * e.z + 0.1f * gv.z / nz;
        v.w = 0.9f * e.w + 0.1f * gv.w / nz;
    } else {
        v = ((const float4*)hn)[(size_t)w * 32 + lane];
    }
    float s  = warp_sum(v.x + v.y + v.z + v.w);
    float ss = warp_sum(v.x * v.x + v.y * v.y + v.z * v.z + v.w * v.w);
    float mean = s * (1.f / 128.f);
    float var = ss * (1.f / 128.f) - mean * mean;
    float r = rsqrtf(var + 1e-5f);
    float4 gg = ((const float4*)g)[lane], bb = ((const float4*)b)[lane];
    v.x = (v.x - mean) * r * gg.x + bb.x;
    v.y = (v.y - mean) * r * gg.y + bb.y;
    v.z = (v.z - mean) * r * gg.z + bb.z;
    v.w = (v.w - mean) * r * gg.w + bb.w;
    if (LRELU) { v.x = lrelu(v.x); v.y = lrelu(v.y); v.z = lrelu(v.z); v.w = lrelu(v.w); }
    ((float4*)out)[(size_t)w * 32 + lane] = v;
}

// Final tiny GEMM: out[Nu,4] = T[Nu,128] @ W2[128,4] + b2. One warp per row.
__global__ void cls2_kernel(const float* __restrict__ T, const float* __restrict__ W2,
                            const float* __restrict__ b2, float* __restrict__ out, int Nr) {
    int w = (blockIdx.x * blockDim.x + threadIdx.x) >> 5;
    int lane = threadIdx.x & 31;
    if (w >= Nr) return;
    float4 t = ((const float4*)T)[(size_t)w * 32 + lane];
    float tv[4] = {t.x, t.y, t.z, t.w};
    float a0 = 0.f, a1 = 0.f, a2 = 0.f, a3 = 0.f;
    const float4* W4 = (const float4*)W2;  // row k of [128][4] = one float4
#pragma unroll
    for (int j = 0; j < 4; j++) {
        float4 wr = W4[lane * 4 + j];
        a0 += tv[j] * wr.x; a1 += tv[j] * wr.y; a2 += tv[j] * wr.z; a3 += tv[j] * wr.w;
    }
    a0 = warp_sum(a0); a1 = warp_sum(a1); a2 = warp_sum(a2); a3 = warp_sum(a3);
    if (lane == 0) {
        out[(size_t)w * 4 + 0] = a0 + b2[0];
        out[(size_t)w * 4 + 1] = a1 + b2[1];
        out[(size_t)w * 4 + 2] = a2 + b2[2];
        out[(size_t)w * 4 + 3] = a3 + b2[3];
    }
}

// ---------------------------------------------------------------------------
// Host orchestration
// ---------------------------------------------------------------------------
extern "C" void kernel_launch(void* const* d_in, const int* in_sizes, int n_in,
                              void* d_out, int out_size) {
    const float* user_x      = (const float*)d_in[0];
    const float* post_x      = (const float*)d_in[1];
    const float* parent_feat = (const float*)d_in[2];
    const float* user_proj_W = (const float*)d_in[3];
    const float* user_proj_b = (const float*)d_in[4];
    const float* post_proj_W = (const float*)d_in[5];
    const float* post_proj_b = (const float*)d_in[6];
    const float* conv_W      = (const float*)d_in[7];
    const float* conv_b      = (const float*)d_in[8];
    const float* conv_g      = (const float*)d_in[9];
    const float* conv_beta   = (const float*)d_in[10];
    const float* uce_W       = (const float*)d_in[11];
    const float* uce_b       = (const float*)d_in[12];
    const float* Wself       = (const float*)d_in[13];
    const float* bself       = (const float*)d_in[14];
    const float* Wneigh      = (const float*)d_in[15];
    const float* bneigh      = (const float*)d_in[16];
    const float* ln_user_g   = (const float*)d_in[17];
    const float* ln_user_b   = (const float*)d_in[18];
    const float* ln_post_g   = (const float*)d_in[19];
    const float* ln_post_b   = (const float*)d_in[20];
    const float* cls_W1      = (const float*)d_in[21];
    const float* cls_b1      = (const float*)d_in[22];
    const float* cls_W2      = (const float*)d_in[23];
    const float* cls_b2      = (const float*)d_in[24];
    const int* publish_u     = (const int*)d_in[25];
    const int* publish_v     = (const int*)d_in[26];
    const int* comment_u     = (const int*)d_in[27];
    const int* comment_v     = (const int*)d_in[28];
    const int* ucu_u         = (const int*)d_in[29];
    const int* ucu_v         = (const int*)d_in[30];
    float* out = (float*)d_out;

    Scratch* S = nullptr;
    cudaGetSymbolAddress((void**)&S, gS);

    // --- zero the per-launch accumulators -----------------------------------
    cudaMemsetAsync(S->cnt_pub_u, 0, sizeof(int) * (size_t)(4 * Nu + 2 * Np), 0);
    cudaMemsetAsync(S->nz, 0, sizeof(int) * 2, 0);
    cudaMemsetAsync(S->avgpost, 0, sizeof(float) * IN, 0);
    cudaMemsetAsync(S->ctx, 0, sizeof(float) * (size_t)Nu * H, 0);

    // --- degrees / counts / constants ---------------------------------------
    count_kernel<<<(Ep + 255) / 256, 256>>>(publish_u, Ep, S->cnt_pub_u);
    count_kernel<<<(Ep + 255) / 256, 256>>>(publish_v, Ep, S->cnt_pub_v);
    count_kernel<<<(Ec + 255) / 256, 256>>>(comment_u, Ec, S->cnt_com_u);
    count_kernel<<<(Ec + 255) / 256, 256>>>(comment_v, Ec, S->cnt_com_v);
    count_kernel<<<(Eu + 255) / 256, 256>>>(ucu_u, Eu, S->cnt_ucu_u);
    count_kernel<<<(Eu + 255) / 256, 256>>>(ucu_v, Eu, S->cnt_ucu_v);
    prep_user_kernel<<<(Nu + 255) / 256, 256>>>();
    prep_post_kernel<<<(Np + 255) / 256, 256>>>();
    avgpost_kernel<<<128, 256>>>(post_x);
    cvec_kernel<<<1, 128>>>(conv_W, conv_b);
    wsum_kernel<<<(2 * HH + 255) / 256, 256>>>(Wself, bself);

    // --- input projections ----------------------------------------------------
    gemm128<1, false, false><<<(Nu + 63) / 64, 256>>>(user_x, user_proj_W, user_proj_b, nullptr, S->h_user, Nu, IN);
    cudaMemcpyAsync(S->init_user, S->h_user, sizeof(float) * (size_t)Nu * H, cudaMemcpyDeviceToDevice, 0);
    gemm128<1, false, false><<<(Np + 63) / 64, 256>>>(post_x, post_proj_W, post_proj_b, nullptr, S->h_post, Np, IN);
    cudaMemcpyAsync(S->init_post, S->h_post, sizeof(float) * (size_t)Np * H, cudaMemcpyDeviceToDevice, 0);
    gemm128<2, false, false><<<(Np + 63) / 64, 256>>>(post_x, uce_W, uce_b, nullptr, S->post_enc, Np, IN);

    // --- ctx -------------------------------------------------------------------
    conv_kernel<<<(Eu + 63) / 64, 256>>>(parent_feat, conv_W, S->cvec, conv_g, conv_beta, ucu_u, S->ctx, Eu);
    ctx_post_kernel<<<(Ec * 32 + 255) / 256, 256>>>(comment_v, comment_u, Ec, 0.3f, S->inv_com_u, S->post_enc, S->ctx);
    ctx_post_kernel<<<(Ep * 32 + 255) / 256, 256>>>(publish_v, publish_u, Ep, 0.5f, S->inv_pub_u, S->post_enc, S->ctx);
    blend_kernel<<<(Nu * H + 255) / 256, 256>>>();

    // --- SAGE layers -------------------------------------------------------------
    for (int l = 0; l < 2; l++) {
        cudaMemsetAsync(S->agg_ucu, 0, sizeof(float) * (size_t)Nu * H, 0);
        cudaMemsetAsync(S->agg_pub, 0, sizeof(float) * (size_t)Np * H * 2, 0);  // agg_pub + agg_com
        scatter_kernel<<<(Ep * 32 + 255) / 256, 256>>>(publish_u, publish_v, Ep, S->h_user, S->agg_pub);
        scatter_kernel<<<(Ec * 32 + 255) / 256, 256>>>(comment_u, comment_v, Ec, S->h_user, S->agg_com);
        scatter_kernel<<<(Eu * 32 + 255) / 256, 256>>>(ucu_u, ucu_v, Eu, S->h_user, S->agg_ucu);

        gemm128<0, false, false><<<(Np + 63) / 64, 256>>>(S->h_post, S->Wsum + (size_t)l * HH, S->bsum + l * H, nullptr, S->post_new, Np, H);
        gemm128<0, true, true><<<(Np + 63) / 64, 256>>>(S->agg_pub, Wneigh + (size_t)(l * 3 + 0) * HH, bneigh + (l * 3 + 0) * H, S->inv_pub_v, S->post_new, Np, H);
        gemm128<0, true, true><<<(Np + 63) / 64, 256>>>(S->agg_com, Wneigh + (size_t)(l * 3 + 1) * HH, bneigh + (l * 3 + 1) * H, S->inv_com_v, S->post_new, Np, H);
        gemm128<0, false, false><<<(Nu + 63) / 64, 256>>>(S->h_user, Wself + (size_t)(l * 3 + 2) * HH, bself + (l * 3 + 2) * H, nullptr, S->user_new, Nu, H);
        gemm128<0, true, true><<<(Nu + 63) / 64, 256>>>(S->agg_ucu, Wneigh + (size_t)(l * 3 + 2) * HH, bneigh + (l * 3 + 2) * H, S->inv_ucu_v, S->user_new, Nu, H);

        cudaMemsetAsync(S->gm_user, 0, sizeof(float) * 2 * H, 0);  // gm_user + gm_post
        colsum_kernel<<<512, 256>>>(S->user_new, S->deg_user, Nu, S->gm_user);
        colsum_kernel<<<512, 256>>>(S->post_new, S->deg_post, Np, S->gm_post);
        if (l == 0) {
            fix_ln_kernel<true><<<((size_t)Nu * 32 + 255) / 256, 256>>>(S->user_new, S->init_user, S->deg_user, S->gm_user, &S->nz[0], ln_user_g, ln_user_b, Nu, S->h_user);
            fix_ln_kernel<true><<<((size_t)Np * 32 + 255) / 256, 256>>>(S->post_new, S->init_post, S->deg_post, S->gm_post, &S->nz[1], ln_post_g, ln_post_b, Np, S->h_post);
        } else {
            fix_ln_kernel<false><<<((size_t)Nu * 32 + 255) / 256, 256>>>(S->user_new, S->init_user, S->deg_user, S->gm_user, &S->nz[0], ln_user_g, ln_user_b, Nu, S->h_user);
            fix_ln_kernel<false><<<((size_t)Np * 32 + 255) / 256, 256>>>(S->post_new, S->init_post, S->deg_post, S->gm_post, &S->nz[1], ln_post_g, ln_post_b, Np, S->h_post);
        }
    }

    // --- classifier ---------------------------------------------------------------
    gemm128<1, false, false><<<(Nu + 63) / 64, 256>>>(S->h_user, cls_W1, cls_b1, nullptr, S->user_new, Nu, H);
    cls2_kernel<<<((size_t)Nu * 32 + 255) / 256, 256>>>(S->user_new, cls_W2, cls_b2, out, Nu);
}

// round 7
// speedup vs baseline: 1.1397x; 1.1397x over previous
#include <cuda_runtime.h>

// ---------------------------------------------------------------------------
// Problem constants
// ---------------------------------------------------------------------------
constexpr int Nu = 50000, Np = 20000, IN = 256, EF = 64, H = 128;
constexpr int Ep = 200000, Ec = 800000, Eu = 300000;
constexpr int HH = H * H;

// ---------------------------------------------------------------------------
// Scratch (device global; allocation-free contract)
// ---------------------------------------------------------------------------
struct alignas(16) Scratch {
    float h_user[(size_t)Nu * H];
    float init_user[(size_t)Nu * H];
    float ctx[(size_t)Nu * H];
    float user_new[(size_t)Nu * H];   // also reused as classifier tmp
    float agg_ucu[(size_t)Nu * H];
    float h_post[(size_t)Np * H];
    float init_post[(size_t)Np * H];
    float post_enc[(size_t)Np * H];
    float post_new[(size_t)Np * H];
    float agg_pub[(size_t)Np * H];
    float agg_com[(size_t)Np * H];
    int cnt_pub_u[Nu]; int cnt_com_u[Nu]; int cnt_ucu_u[Nu]; int cnt_ucu_v[Nu];
    int cnt_pub_v[Np]; int cnt_com_v[Np];
    float inv_pub_u[Nu]; float inv_com_u[Nu]; float inv_ucu_v[Nu];
    float inv_pub_v[Np]; float inv_com_v[Np];
    int deg_user[Nu]; int deg_post[Np];
    float avgpost[IN];
    float cvec[H];
    float gm_user[H]; float gm_post[H];   // contiguous: single memset
    int nz[4];                            // padded so next member is 16B-aligned
    // tf32-converted, n-major (Wt[n][k]) weights. 16B alignment REQUIRED for
    // the uint4 loads in gemm_tf32 (this was the R3 misaligned-address crash).
    alignas(16) unsigned Wt_up[128 * 256];
    alignas(16) unsigned Wt_pp[128 * 256];
    alignas(16) unsigned Wt_uce[128 * 256];
    alignas(16) unsigned Wt_cls[128 * 128];
    alignas(16) unsigned Wt_ss[2][HH];   // Wself(l,0)+Wself(l,1)
    alignas(16) unsigned Wt_n0[2][HH];
    alignas(16) unsigned Wt_n1[2][HH];
    alignas(16) unsigned Wt_s2[2][HH];
    alignas(16) unsigned Wt_n2[2][HH];
    float b_post[2][H]; float b_user[2][H];
};
__device__ Scratch gS;

// ---------------------------------------------------------------------------
// Helpers
// ---------------------------------------------------------------------------
__device__ __forceinline__ float warp_sum(float v) {
#pragma unroll
    for (int o = 16; o; o >>= 1) v += __shfl_xor_sync(0xffffffffu, v, o);
    return v;
}

__device__ __forceinline__ void red4(float* p, float4 v) {
    asm volatile("red.global.add.v4.f32 [%0], {%1,%2,%3,%4};"
                 :: "l"(p), "f"(v.x), "f"(v.y), "f"(v.z), "f"(v.w) : "memory");
}

__device__ __forceinline__ float lrelu(float x) { return x >= 0.f ? x : 0.01f * x; }

__device__ __forceinline__ unsigned f2tf(float x) {
    unsigned r;
    asm("cvt.rna.tf32.f32 %0, %1;" : "=r"(r) : "f"(x));
    return r;
}

__device__ __forceinline__ void mma_tf32(float c[4], const unsigned a[4], const unsigned b[2]) {
    asm volatile(
        "mma.sync.aligned.m16n8k8.row.col.f32.tf32.tf32.f32 "
        "{%0,%1,%2,%3},{%4,%5,%6,%7},{%8,%9},{%0,%1,%2,%3};"
        : "+f"(c[0]), "+f"(c[1]), "+f"(c[2]), "+f"(c[3])
        : "r"(a[0]), "r"(a[1]), "r"(a[2]), "r"(a[3]), "r"(b[0]), "r"(b[1]));
}

// ---------------------------------------------------------------------------
// tf32 tensor-core GEMM with up to 3 fused K-segments:
//   C[M,128] = act( sum_s (rs_s ⊙ A_s[M,Ks]) @ W_s[Ks,128]  + bias )
// W is pre-transposed+tf32 (Wt[n][k], n-major). BM=128,BN=128,BK=16.
// 8 warps, each computes a 32x64 tile via m16n8k8 mma.
// If C2 != nullptr, the activated result is also written to C2 (fused copy).
// ---------------------------------------------------------------------------
struct Seg { const float* A; const unsigned* Wt; const float* rs; int K; };

template <int ACT>
__global__ __launch_bounds__(256, 2) void gemm_tf32(
    Seg s0, Seg s1, Seg s2, int nseg,
    const float* __restrict__ bias, float* __restrict__ C,
    float* __restrict__ C2, int M)
{
    __shared__ __align__(16) unsigned As[128][20];
    __shared__ __align__(16) unsigned Bs[128][20];
    const int tid = threadIdx.x;
    const int lane = tid & 31, warp = tid >> 5;
    const int gid = lane >> 2, q = lane & 3;
    const int wm = warp & 3, wn = warp >> 2;
    const int rowBase = blockIdx.x * 128;
    const int lrow = tid >> 2;            // 0..63
    const int lk4 = (tid & 3) * 4;        // 0,4,8,12

    float acc[2][8][4];
#pragma unroll
    for (int mt = 0; mt < 2; mt++)
#pragma unroll
        for (int nt = 0; nt < 8; nt++)
#pragma unroll
            for (int i = 0; i < 4; i++) acc[mt][nt][i] = 0.f;

    Seg segs[3] = {s0, s1, s2};
    for (int s = 0; s < nseg; s++) {
        const float* A = segs[s].A;
        const unsigned* Wt = segs[s].Wt;
        const float* rs = segs[s].rs;
        const int K = segs[s].K;
        int r0 = rowBase + lrow;      if (r0 > M - 1) r0 = M - 1;
        int r1 = rowBase + lrow + 64; if (r1 > M - 1) r1 = M - 1;
        const float sc0 = rs ? rs[r0] : 1.f;
        const float sc1 = rs ? rs[r1] : 1.f;

        for (int k0 = 0; k0 < K; k0 += 16) {
            float4 av0 = *(const float4*)&A[(size_t)r0 * K + k0 + lk4];
            float4 av1 = *(const float4*)&A[(size_t)r1 * K + k0 + lk4];
            uint4 u0 = make_uint4(f2tf(av0.x * sc0), f2tf(av0.y * sc0),
                                  f2tf(av0.z * sc0), f2tf(av0.w * sc0));
            uint4 u1 = make_uint4(f2tf(av1.x * sc1), f2tf(av1.y * sc1),
                                  f2tf(av1.z * sc1), f2tf(av1.w * sc1));
            *(uint4*)&As[lrow][lk4] = u0;
            *(uint4*)&As[lrow + 64][lk4] = u1;
            *(uint4*)&Bs[lrow][lk4]      = *(const uint4*)&Wt[(size_t)lrow * K + k0 + lk4];
            *(uint4*)&Bs[lrow + 64][lk4] = *(const uint4*)&Wt[(size_t)(lrow + 64) * K + k0 + lk4];
            __syncthreads();

#pragma unroll
            for (int kk = 0; kk < 16; kk += 8) {
                unsigned a[2][4], b[8][2];
#pragma unroll
                for (int mt = 0; mt < 2; mt++) {
                    int r = wm * 32 + mt * 16 + gid;
                    a[mt][0] = As[r][kk + q];
                    a[mt][1] = As[r + 8][kk + q];
                    a[mt][2] = As[r][kk + q + 4];
                    a[mt][3] = As[r + 8][kk + q + 4];
                }
#pragma unroll
                for (int nt = 0; nt < 8; nt++) {
                    int n = wn * 64 + nt * 8 + gid;
                    b[nt][0] = Bs[n][kk + q];
                    b[nt][1] = Bs[n][kk + q + 4];
                }
#pragma unroll
                for (int mt = 0; mt < 2; mt++)
#pragma unroll
                    for (int nt = 0; nt < 8; nt++)
                        mma_tf32(acc[mt][nt], a[mt], b[nt]);
            }
            __syncthreads();
        }
    }

    // Epilogue: bias + activation + store (c0,c1 = row gid; c2,c3 = row gid+8)
#pragma unroll
    for (int mt = 0; mt < 2; mt++) {
        int row0 = rowBase + wm * 32 + mt * 16 + gid;
        int row1 = row0 + 8;
#pragma unroll
        for (int nt = 0; nt < 8; nt++) {
            int col = wn * 64 + nt * 8 + q * 2;
            float b0 = bias[col], b1 = bias[col + 1];
            float v0 = acc[mt][nt][0] + b0, v1 = acc[mt][nt][1] + b1;
            float v2 = acc[mt][nt][2] + b0, v3 = acc[mt][nt][3] + b1;
            if (ACT == 1) { v0 = lrelu(v0); v1 = lrelu(v1); v2 = lrelu(v2); v3 = lrelu(v3); }
            if (ACT == 2) {
                v0 = fmaxf(v0, 0.f); v1 = fmaxf(v1, 0.f);
                v2 = fmaxf(v2, 0.f); v3 = fmaxf(v3, 0.f);
            }
            if (row0 < M) {
                *(float2*)&C[(size_t)row0 * 128 + col] = make_float2(v0, v1);
                if (C2) *(float2*)&C2[(size_t)row0 * 128 + col] = make_float2(v0, v1);
            }
            if (row1 < M) {
                *(float2*)&C[(size_t)row1 * 128 + col] = make_float2(v2, v3);
                if (C2) *(float2*)&C2[(size_t)row1 * 128 + col] = make_float2(v2, v3);
            }
        }
    }
}

// ---------------------------------------------------------------------------
// Weight preprocessing: dst[n*K+k] = tf32(src[k*128+n] (+ src2[k*128+n]))
// ---------------------------------------------------------------------------
struct WJob { const float* src; const float* src2; unsigned* dst; int K; };
struct WJobs { WJob j[14]; };

__global__ void wprep_kernel(WJobs js) {
    WJob J = js.j[blockIdx.y];
    int idx = blockIdx.x * 256 + threadIdx.x;
    if (idx >= 128 * J.K) return;
    int n = idx / J.K, k = idx % J.K;
    float v = J.src[(size_t)k * 128 + n];
    if (J.src2) v += J.src2[(size_t)k * 128 + n];
    J.dst[idx] = f2tf(v);
}

__global__ void bcomb_kernel(const float* __restrict__ bself, const float* __restrict__ bneigh) {
    int c = threadIdx.x;  // 128
#pragma unroll
    for (int l = 0; l < 2; l++) {
        gS.b_post[l][c] = bself[(l * 3 + 0) * H + c] + bself[(l * 3 + 1) * H + c]
                        + bneigh[(l * 3 + 0) * H + c] + bneigh[(l * 3 + 1) * H + c];
        gS.b_user[l][c] = bself[(l * 3 + 2) * H + c] + bneigh[(l * 3 + 2) * H + c];
    }
}

// ---------------------------------------------------------------------------
// Fused conversation-context kernel (fp32 GEMM K=64 + row-LN + relu + scatter)
// ---------------------------------------------------------------------------
__global__ void conv_kernel(const float* __restrict__ A, const float* __restrict__ W,
                            const float* __restrict__ cvec,
                            const float* __restrict__ gw, const float* __restrict__ be,
                            const int* __restrict__ uidx, float* __restrict__ ctx, int M) {
    __shared__ float As[16][64];
    __shared__ float Ws[16][128];
    const int tid = threadIdx.x;
    const int ty = tid >> 5, tx = tid & 31;
    const int rowBase = blockIdx.x * 64;

    float acc[8][4];
#pragma unroll
    for (int r = 0; r < 8; r++)
#pragma unroll
        for (int c = 0; c < 4; c++) acc[r][c] = 0.f;

    const int arow = tid >> 2;
    const int ak = (tid & 3) * 4;
    int grow = rowBase + arow; if (grow > M - 1) grow = M - 1;

    for (int k0 = 0; k0 < 64; k0 += 16) {
        float4 av = *(const float4*)&A[(size_t)grow * 64 + k0 + ak];
        As[ak + 0][arow] = av.x;
        As[ak + 1][arow] = av.y;
        As[ak + 2][arow] = av.z;
        As[ak + 3][arow] = av.w;
#pragma unroll
        for (int t = 0; t < 2; t++) {
            int idx = tid + t * 256;
            int wk = idx >> 5, wc = (idx & 31) * 4;
            *(float4*)&Ws[wk][wc] = *(const float4*)&W[(size_t)(k0 + wk) * 128 + wc];
        }
        __syncthreads();
#pragma unroll
        for (int kk = 0; kk < 16; kk++) {
            float4 a0 = *(const float4*)&As[kk][ty * 8];
            float4 a1 = *(const float4*)&As[kk][ty * 8 + 4];
            float4 b  = *(const float4*)&Ws[kk][tx * 4];
            float ar[8] = {a0.x, a0.y, a0.z, a0.w, a1.x, a1.y, a1.z, a1.w};
#pragma unroll
            for (int r = 0; r < 8; r++) {
                acc[r][0] += ar[r] * b.x;
                acc[r][1] += ar[r] * b.y;
                acc[r][2] += ar[r] * b.z;
                acc[r][3] += ar[r] * b.w;
            }
        }
        __syncthreads();
    }

    float4 cv = ((const float4*)cvec)[tx];
    float4 gg = ((const float4*)gw)[tx];
    float4 bb = ((const float4*)be)[tx];
#pragma unroll
    for (int r = 0; r < 8; r++) {
        int row = rowBase + ty * 8 + r;
        float v0 = acc[r][0] + cv.x, v1 = acc[r][1] + cv.y;
        float v2 = acc[r][2] + cv.z, v3 = acc[r][3] + cv.w;
        float s  = warp_sum(v0 + v1 + v2 + v3);
        float ss = warp_sum(v0 * v0 + v1 * v1 + v2 * v2 + v3 * v3);
        float mean = s * (1.f / 128.f);
        float var = ss * (1.f / 128.f) - mean * mean;
        float rr = rsqrtf(var + 1e-5f);
        v0 = fmaxf((v0 - mean) * rr * gg.x + bb.x, 0.f);
        v1 = fmaxf((v1 - mean) * rr * gg.y + bb.y, 0.f);
        v2 = fmaxf((v2 - mean) * rr * gg.z + bb.z, 0.f);
        v3 = fmaxf((v3 - mean) * rr * gg.w + bb.w, 0.f);
        if (row < M) {
            int u = uidx[row];
            red4(&ctx[(size_t)u * 128 + tx * 4], make_float4(v0, v1, v2, v3));
        }
    }
}

// ---------------------------------------------------------------------------
// Small kernels
// ---------------------------------------------------------------------------
struct CJob { const int* idx; int n; int* cnt; };
__global__ void count6_kernel(CJob a, CJob b, CJob c, CJob d, CJob e, CJob f) {
    CJob js[6] = {a, b, c, d, e, f};
    CJob J = js[blockIdx.y];
    int i = blockIdx.x * 256 + threadIdx.x;
    if (i < J.n) atomicAdd(&J.cnt[J.idx[i]], 1);
}

__global__ void prep_user_kernel() {
    int i = blockIdx.x * blockDim.x + threadIdx.x;
    int flag = 0;
    if (i < Nu) {
        int a = gS.cnt_pub_u[i], b = gS.cnt_com_u[i];
        int c = gS.cnt_ucu_u[i], d = gS.cnt_ucu_v[i];
        gS.inv_pub_u[i] = 1.f / (float)(a > 1 ? a : 1);
        gS.inv_com_u[i] = 1.f / (float)(b > 1 ? b : 1);
        gS.inv_ucu_v[i] = 1.f / (float)(d > 1 ? d : 1);
        int deg = a + b + c + d;
        gS.deg_user[i] = deg;
        flag = deg > 0;
    }
    unsigned m = __ballot_sync(0xffffffffu, flag);
    if ((threadIdx.x & 31) == 0) atomicAdd(&gS.nz[0], __popc(m));
}

__global__ void prep_post_kernel() {
    int i = blockIdx.x * blockDim.x + threadIdx.x;
    int flag = 0;
    if (i < Np) {
        int a = gS.cnt_pub_v[i], b = gS.cnt_com_v[i];
        gS.inv_pub_v[i] = 1.f / (float)(a > 1 ? a : 1);
        gS.inv_com_v[i] = 1.f / (float)(b > 1 ? b : 1);
        int deg = a + b;
        gS.deg_post[i] = deg;
        flag = deg > 0;
    }
    unsigned m = __ballot_sync(0xffffffffu, flag);
    if ((threadIdx.x & 31) == 0) atomicAdd(&gS.nz[1], __popc(m));
}

__global__ void avgpost_kernel(const float* __restrict__ post_x) {
    int col = threadIdx.x;                 // 256 threads = 256 cols
    float s = 0.f;
    for (int r = blockIdx.x; r < Np; r += gridDim.x)
        s += post_x[(size_t)r * IN + col];
    atomicAdd(&gS.avgpost[col], s);
}

__global__ void cvec_kernel(const float* __restrict__ conv_W, const float* __restrict__ conv_b) {
    int c = threadIdx.x;                   // 128 threads
    float s = conv_b[c];
    const float scale = 1.f / (float)Np;
    for (int k = 0; k < IN; k++)
        s += gS.avgpost[k] * scale * conv_W[(size_t)(EF + k) * H + c];
    gS.cvec[c] = s;
}

// ctx[u] += coef * inv_u[u] * post_enc[v]   (one warp per edge)
__global__ void ctx_post_kernel(const int* __restrict__ vv, const int* __restrict__ uu, int n,
                                float coef, const float* __restrict__ invu,
                                const float* __restrict__ post_enc, float* __restrict__ ctx) {
    int e = (blockIdx.x * blockDim.x + threadIdx.x) >> 5;
    int lane = threadIdx.x & 31;
    if (e >= n) return;
    int u = uu[e], v = vv[e];
    float s = coef * invu[u];
    float4 p = ((const float4*)post_enc)[(size_t)v * 32 + lane];
    p.x *= s; p.y *= s; p.z *= s; p.w *= s;
    red4(&ctx[(size_t)u * 128 + lane * 4], p);
}

// agg[dst] += src_feat[src]   (one warp per edge)
__global__ void scatter_kernel(const int* __restrict__ src, const int* __restrict__ dst, int n,
                               const float* __restrict__ sbuf, float* __restrict__ dbuf) {
    int e = (blockIdx.x * blockDim.x + threadIdx.x) >> 5;
    int lane = threadIdx.x & 31;
    if (e >= n) return;
    int s = src[e], d = dst[e];
    float4 v = ((const float4*)sbuf)[(size_t)s * 32 + lane];
    red4(&dbuf[(size_t)d * 128 + lane * 4], v);
}

__global__ void blend_kernel() {
    size_t i = (size_t)blockIdx.x * blockDim.x + threadIdx.x;
    if (i < (size_t)Nu * H)
        gS.h_user[i] = 0.7f * gS.h_user[i] + 0.3f * gS.ctx[i];
}

// Column sums over rows with deg>0
__global__ void colsum_kernel(const float* __restrict__ buf, const int* __restrict__ deg,
                              int Nr, float* __restrict__ gm) {
    __shared__ float s[128];
    if (threadIdx.x < 128) s[threadIdx.x] = 0.f;
    __syncthreads();
    int col = threadIdx.x & 127, sub = threadIdx.x >> 7;
    float local = 0.f;
    for (int r = blockIdx.x * 2 + sub; r < Nr; r += gridDim.x * 2)
        if (deg[r] > 0) local += buf[(size_t)r * 128 + col];
    atomicAdd(&s[col], local);
    __syncthreads();
    if (threadIdx.x < 128) atomicAdd(&gm[threadIdx.x], s[threadIdx.x]);
}

// fix_zero_degree + LayerNorm (+ optional leaky relu). One warp per row.
template <bool LRELU>
__global__ void fix_ln_kernel(const float* __restrict__ hn, const float* __restrict__ init,
                              const int* __restrict__ deg, const float* __restrict__ gm,
                              const int* __restrict__ nzp,
                              const float* __restrict__ g, const float* __restrict__ b,
                              int Nr, float* __restrict__ out) {
    int w = (blockIdx.x * blockDim.x + threadIdx.x) >> 5;
    int lane = threadIdx.x & 31;
    if (w >= Nr) return;
    float4 v;
    if (deg[w] == 0) {
        float nz = fmaxf((float)(*nzp), 1.f);
        float4 e = ((const float4*)init)[(size_t)w * 32 + lane];
        float4 gv = ((const float4*)gm)[lane];
        v.x = 0.9f * e.x + 0.1f * gv.x / nz;
        v.y = 0.9f * e.y + 0.1f * gv.y / nz;
        v.z = 0.9f * e.z + 0.1f * gv.z / nz;
        v.w = 0.9f * e.w + 0.1f * gv.w / nz;
    } else {
        v = ((const float4*)hn)[(size_t)w * 32 + lane];
    }
    float s  = warp_sum(v.x + v.y + v.z + v.w);
    float ss = warp_sum(v.x * v.x + v.y * v.y + v.z * v.z + v.w * v.w);
    float mean = s * (1.f / 128.f);
    float var = ss * (1.f / 128.f) - mean * mean;
    float r = rsqrtf(var + 1e-5f);
    float4 gg = ((const float4*)g)[lane], bb = ((const float4*)b)[lane];
    v.x = (v.x - mean) * r * gg.x + bb.x;
    v.y = (v.y - mean) * r * gg.y + bb.y;
    v.z = (v.z - mean) * r * gg.z + bb.z;
    v.w = (v.w - mean) * r * gg.w + bb.w;
    if (LRELU) { v.x = lrelu(v.x); v.y = lrelu(v.y); v.z = lrelu(v.z); v.w = lrelu(v.w); }
    ((float4*)out)[(size_t)w * 32 + lane] = v;
}

// Final tiny GEMM: out[Nu,4] = T[Nu,128] @ W2[128,4] + b2. One warp per row.
__global__ void cls2_kernel(const float* __restrict__ T, const float* __restrict__ W2,
                            const float* __restrict__ b2, float* __restrict__ out, int Nr) {
    int w = (blockIdx.x * blockDim.x + threadIdx.x) >> 5;
    int lane = threadIdx.x & 31;
    if (w >= Nr) return;
    float4 t = ((const float4*)T)[(size_t)w * 32 + lane];
    float tv[4] = {t.x, t.y, t.z, t.w};
    float a0 = 0.f, a1 = 0.f, a2 = 0.f, a3 = 0.f;
    const float4* W4 = (const float4*)W2;  // row k of [128][4] = one float4
#pragma unroll
    for (int j = 0; j < 4; j++) {
        float4 wr = W4[lane * 4 + j];
        a0 += tv[j] * wr.x; a1 += tv[j] * wr.y; a2 += tv[j] * wr.z; a3 += tv[j] * wr.w;
    }
    a0 = warp_sum(a0); a1 = warp_sum(a1); a2 = warp_sum(a2); a3 = warp_sum(a3);
    if (lane == 0) {
        out[(size_t)w * 4 + 0] = a0 + b2[0];
        out[(size_t)w * 4 + 1] = a1 + b2[1];
        out[(size_t)w * 4 + 2] = a2 + b2[2];
        out[(size_t)w * 4 + 3] = a3 + b2[3];
    }
}

// ---------------------------------------------------------------------------
// Host orchestration
// ---------------------------------------------------------------------------
extern "C" void kernel_launch(void* const* d_in, const int* in_sizes, int n_in,
                              void* d_out, int out_size) {
    const float* user_x      = (const float*)d_in[0];
    const float* post_x      = (const float*)d_in[1];
    const float* parent_feat = (const float*)d_in[2];
    const float* user_proj_W = (const float*)d_in[3];
    const float* user_proj_b = (const float*)d_in[4];
    const float* post_proj_W = (const float*)d_in[5];
    const float* post_proj_b = (const float*)d_in[6];
    const float* conv_W      = (const float*)d_in[7];
    const float* conv_b      = (const float*)d_in[8];
    const float* conv_g      = (const float*)d_in[9];
    const float* conv_beta   = (const float*)d_in[10];
    const float* uce_W       = (const float*)d_in[11];
    const float* uce_b       = (const float*)d_in[12];
    const float* Wself       = (const float*)d_in[13];
    const float* bself       = (const float*)d_in[14];
    const float* Wneigh      = (const float*)d_in[15];
    const float* bneigh      = (const float*)d_in[16];
    const float* ln_user_g   = (const float*)d_in[17];
    const float* ln_user_b   = (const float*)d_in[18];
    const float* ln_post_g   = (const float*)d_in[19];
    const float* ln_post_b   = (const float*)d_in[20];
    const float* cls_W1      = (const float*)d_in[21];
    const float* cls_b1      = (const float*)d_in[22];
    const float* cls_W2      = (const float*)d_in[23];
    const float* cls_b2      = (const float*)d_in[24];
    const int* publish_u     = (const int*)d_in[25];
    const int* publish_v     = (const int*)d_in[26];
    const int* comment_u     = (const int*)d_in[27];
    const int* comment_v     = (const int*)d_in[28];
    const int* ucu_u         = (const int*)d_in[29];
    const int* ucu_v         = (const int*)d_in[30];
    float* out = (float*)d_out;

    Scratch* S = nullptr;
    cudaGetSymbolAddress((void**)&S, gS);

    // --- zero per-launch accumulators ---------------------------------------
    cudaMemsetAsync(S->cnt_pub_u, 0, sizeof(int) * (size_t)(4 * Nu + 2 * Np), 0);
    cudaMemsetAsync(S->nz, 0, sizeof(int) * 4, 0);
    cudaMemsetAsync(S->avgpost, 0, sizeof(float) * IN, 0);
    cudaMemsetAsync(S->ctx, 0, sizeof(float) * (size_t)Nu * H, 0);

    // --- counts / degrees / constants ---------------------------------------
    {
        CJob c0 = {publish_u, Ep, S->cnt_pub_u};
        CJob c1 = {publish_v, Ep, S->cnt_pub_v};
        CJob c2 = {comment_u, Ec, S->cnt_com_u};
        CJob c3 = {comment_v, Ec, S->cnt_com_v};
        CJob c4 = {ucu_u, Eu, S->cnt_ucu_u};
        CJob c5 = {ucu_v, Eu, S->cnt_ucu_v};
        dim3 g((Ec + 255) / 256, 6);
        count6_kernel<<<g, 256>>>(c0, c1, c2, c3, c4, c5);
    }
    prep_user_kernel<<<(Nu + 255) / 256, 256>>>();
    prep_post_kernel<<<(Np + 255) / 256, 256>>>();
    avgpost_kernel<<<128, 256>>>(post_x);
    cvec_kernel<<<1, 128>>>(conv_W, conv_b);

    // --- weight preprocessing (transpose + tf32) -----------------------------
    {
        WJobs js;
        js.j[0] = {user_proj_W, nullptr, S->Wt_up, 256};
        js.j[1] = {post_proj_W, nullptr, S->Wt_pp, 256};
        js.j[2] = {uce_W, nullptr, S->Wt_uce, 256};
        js.j[3] = {cls_W1, nullptr, S->Wt_cls, 128};
        for (int l = 0; l < 2; l++) {
            js.j[4 + 5 * l + 0] = {Wself + (size_t)(l * 3 + 0) * HH, Wself + (size_t)(l * 3 + 1) * HH, S->Wt_ss[l], 128};
            js.j[4 + 5 * l + 1] = {Wneigh + (size_t)(l * 3 + 0) * HH, nullptr, S->Wt_n0[l], 128};
            js.j[4 + 5 * l + 2] = {Wneigh + (size_t)(l * 3 + 1) * HH, nullptr, S->Wt_n1[l], 128};
            js.j[4 + 5 * l + 3] = {Wself + (size_t)(l * 3 + 2) * HH, nullptr, S->Wt_s2[l], 128};
            js.j[4 + 5 * l + 4] = {Wneigh + (size_t)(l * 3 + 2) * HH, nullptr, S->Wt_n2[l], 128};
        }
        dim3 g(128, 14);
        wprep_kernel<<<g, 256>>>(js);
    }
    bcomb_kernel<<<1, 128>>>(bself, bneigh);

    Seg z = {nullptr, nullptr, nullptr, 0};

    // --- input projections (tf32); init copies fused into epilogue -----------
    {
        Seg s = {user_x, S->Wt_up, nullptr, 256};
        gemm_tf32<1><<<(Nu + 127) / 128, 256>>>(s, z, z, 1, user_proj_b, S->h_user, S->init_user, Nu);
    }
    {
        Seg s = {post_x, S->Wt_pp, nullptr, 256};
        gemm_tf32<1><<<(Np + 127) / 128, 256>>>(s, z, z, 1, post_proj_b, S->h_post, S->init_post, Np);
    }
    {
        Seg s = {post_x, S->Wt_uce, nullptr, 256};
        gemm_tf32<2><<<(Np + 127) / 128, 256>>>(s, z, z, 1, uce_b, S->post_enc, nullptr, Np);
    }

    // --- ctx ------------------------------------------------------------------
    conv_kernel<<<(Eu + 63) / 64, 256>>>(parent_feat, conv_W, S->cvec, conv_g, conv_beta, ucu_u, S->ctx, Eu);
    ctx_post_kernel<<<(Ec * 32 + 255) / 256, 256>>>(comment_v, comment_u, Ec, 0.3f, S->inv_com_u, S->post_enc, S->ctx);
    ctx_post_kernel<<<(Ep * 32 + 255) / 256, 256>>>(publish_v, publish_u, Ep, 0.5f, S->inv_pub_u, S->post_enc, S->ctx);
    blend_kernel<<<(Nu * H + 255) / 256, 256>>>();

    // --- SAGE layers ----------------------------------------------------------
    for (int l = 0; l < 2; l++) {
        cudaMemsetAsync(S->agg_ucu, 0, sizeof(float) * (size_t)Nu * H, 0);
        cudaMemsetAsync(S->agg_pub, 0, sizeof(float) * (size_t)Np * H * 2, 0);  // agg_pub + agg_com
        scatter_kernel<<<(Ep * 32 + 255) / 256, 256>>>(publish_u, publish_v, Ep, S->h_user, S->agg_pub);
        scatter_kernel<<<(Ec * 32 + 255) / 256, 256>>>(comment_u, comment_v, Ec, S->h_user, S->agg_com);
        scatter_kernel<<<(Eu * 32 + 255) / 256, 256>>>(ucu_u, ucu_v, Eu, S->h_user, S->agg_ucu);

        // post_new = h_post@(Ws0+Ws1) + mean_pub@Wn0 + mean_com@Wn1 + b_post[l]
        {
            Seg sA = {S->h_post, S->Wt_ss[l], nullptr, 128};
            Seg sB = {S->agg_pub, S->Wt_n0[l], S->inv_pub_v, 128};
            Seg sC = {S->agg_com, S->Wt_n1[l], S->inv_com_v, 128};
            gemm_tf32<0><<<(Np + 127) / 128, 256>>>(sA, sB, sC, 3, S->b_post[l], S->post_new, nullptr, Np);
        }
        // user_new = h_user@Ws2 + mean_ucu@Wn2 + b_user[l]
        {
            Seg sA = {S->h_user, S->Wt_s2[l], nullptr, 128};
            Seg sB = {S->agg_ucu, S->Wt_n2[l], S->inv_ucu_v, 128};
            gemm_tf32<0><<<(Nu + 127) / 128, 256>>>(sA, sB, z, 2, S->b_user[l], S->user_new, nullptr, Nu);
        }

        cudaMemsetAsync(S->gm_user, 0, sizeof(float) * 2 * H, 0);  // gm_user + gm_post
        colsum_kernel<<<512, 256>>>(S->user_new, S->deg_user, Nu, S->gm_user);
        colsum_kernel<<<512, 256>>>(S->post_new, S->deg_post, Np, S->gm_post);
        if (l == 0) {
            fix_ln_kernel<true><<<((size_t)Nu * 32 + 255) / 256, 256>>>(S->user_new, S->init_user, S->deg_user, S->gm_user, &S->nz[0], ln_user_g, ln_user_b, Nu, S->h_user);
            fix_ln_kernel<true><<<((size_t)Np * 32 + 255) / 256, 256>>>(S->post_new, S->init_post, S->deg_post, S->gm_post, &S->nz[1], ln_post_g, ln_post_b, Np, S->h_post);
        } else {
            fix_ln_kernel<false><<<((size_t)Nu * 32 + 255) / 256, 256>>>(S->user_new, S->init_user, S->deg_user, S->gm_user, &S->nz[0], ln_user_g, ln_user_b, Nu, S->h_user);
            fix_ln_kernel<false><<<((size_t)Np * 32 + 255) / 256, 256>>>(S->post_new, S->init_post, S->deg_post, S->gm_post, &S->nz[1], ln_post_g, ln_post_b, Np, S->h_post);
        }
    }

    // --- classifier -----------------------------------------------------------
    {
        Seg s = {S->h_user, S->Wt_cls, nullptr, 128};
        gemm_tf32<1><<<(Nu + 127) / 128, 256>>>(s, z, z, 1, cls_b1, S->user_new, nullptr, Nu);
    }
    cls2_kernel<<<((size_t)Nu * 32 + 255) / 256, 256>>>(S->user_new, cls_W2, cls_b2, out, Nu);
}

// round 8
// speedup vs baseline: 1.3782x; 1.2093x over previous
#include <cuda_runtime.h>

// ---------------------------------------------------------------------------
// Problem constants
// ---------------------------------------------------------------------------
constexpr int Nu = 50000, Np = 20000, IN = 256, EF = 64, H = 128;
constexpr int Ep = 200000, Ec = 800000, Eu = 300000;
constexpr int HH = H * H;
constexpr int SCAN_G = 64;

// ---------------------------------------------------------------------------
// Scratch (device global; allocation-free contract)
// ---------------------------------------------------------------------------
struct alignas(16) Scratch {
    float h_user[(size_t)Nu * H];
    float init_user[(size_t)Nu * H];
    float ctx[(size_t)Nu * H];
    float user_new[(size_t)Nu * H];   // also reused as classifier tmp
    float agg_ucu[(size_t)Nu * H];
    float h_post[(size_t)Np * H];
    float init_post[(size_t)Np * H];
    float post_enc[(size_t)Np * H];
    float post_new[(size_t)Np * H];
    float agg_pub[(size_t)Np * H];
    float agg_com[(size_t)Np * H];
    int cnt_pub_u[Nu]; int cnt_com_u[Nu]; int cnt_ucu_u[Nu]; int cnt_ucu_v[Nu];
    int cnt_pub_v[Np]; int cnt_com_v[Np];
    float inv_pub_u[Nu]; float inv_com_u[Nu]; float inv_ucu_v[Nu];
    float inv_pub_v[Np]; float inv_com_v[Np];
    int deg_user[Nu]; int deg_post[Np];
    float avgpost[IN];
    float cvec[H];
    float gm_user[H]; float gm_post[H];   // contiguous: single memset
    int nz[4];                            // padded so next member is 16B-aligned
    // CSR structures (built once per launch)
    int off_pub_v[Np + 1]; int off_com_v[Np + 1]; int off_ucu_v[Nu + 1];
    int off_com_u[Nu + 1]; int off_pub_u[Nu + 1];
    int cur_pub_v[Np]; int cur_com_v[Np]; int cur_ucu_v[Nu];
    int cur_com_u[Nu]; int cur_pub_u[Nu];
    int blocksums[5 * SCAN_G];
    int csr_pub_v[Ep]; int csr_com_v[Ec]; int csr_ucu_v[Eu];
    int csr_com_u[Ec]; int csr_pub_u[Ep];
    // tf32-converted, n-major (Wt[n][k]) weights. 16B alignment REQUIRED for
    // the uint4 loads in gemm_tf32 (this was the R3 misaligned-address crash).
    alignas(16) unsigned Wt_up[128 * 256];
    alignas(16) unsigned Wt_pp[128 * 256];
    alignas(16) unsigned Wt_uce[128 * 256];
    alignas(16) unsigned Wt_cls[128 * 128];
    alignas(16) unsigned Wt_ss[2][HH];   // Wself(l,0)+Wself(l,1)
    alignas(16) unsigned Wt_n0[2][HH];
    alignas(16) unsigned Wt_n1[2][HH];
    alignas(16) unsigned Wt_s2[2][HH];
    alignas(16) unsigned Wt_n2[2][HH];
    float b_post[2][H]; float b_user[2][H];
};
__device__ Scratch gS;

// ---------------------------------------------------------------------------
// Helpers
// ---------------------------------------------------------------------------
__device__ __forceinline__ float warp_sum(float v) {
#pragma unroll
    for (int o = 16; o; o >>= 1) v += __shfl_xor_sync(0xffffffffu, v, o);
    return v;
}

__device__ __forceinline__ void red4(float* p, float4 v) {
    asm volatile("red.global.add.v4.f32 [%0], {%1,%2,%3,%4};"
                 :: "l"(p), "f"(v.x), "f"(v.y), "f"(v.z), "f"(v.w) : "memory");
}

__device__ __forceinline__ float lrelu(float x) { return x >= 0.f ? x : 0.01f * x; }

__device__ __forceinline__ unsigned f2tf(float x) {
    unsigned r;
    asm("cvt.rna.tf32.f32 %0, %1;" : "=r"(r) : "f"(x));
    return r;
}

__device__ __forceinline__ void mma_tf32(float c[4], const unsigned a[4], const unsigned b[2]) {
    asm volatile(
        "mma.sync.aligned.m16n8k8.row.col.f32.tf32.tf32.f32 "
        "{%0,%1,%2,%3},{%4,%5,%6,%7},{%8,%9},{%0,%1,%2,%3};"
        : "+f"(c[0]), "+f"(c[1]), "+f"(c[2]), "+f"(c[3])
        : "r"(a[0]), "r"(a[1]), "r"(a[2]), "r"(a[3]), "r"(b[0]), "r"(b[1]));
}

// Gather-sum a 512B feature row range via CSR (dual accumulator for MLP=2).
__device__ __forceinline__ float4 gath(const int* __restrict__ csr, int beg, int end,
                                       const float* __restrict__ feat, int lane) {
    float4 a = make_float4(0.f, 0.f, 0.f, 0.f);
    float4 b = make_float4(0.f, 0.f, 0.f, 0.f);
    int i = beg;
    for (; i + 1 < end; i += 2) {
        int s0 = csr[i], s1 = csr[i + 1];
        float4 v0 = ((const float4*)feat)[(size_t)s0 * 32 + lane];
        float4 v1 = ((const float4*)feat)[(size_t)s1 * 32 + lane];
        a.x += v0.x; a.y += v0.y; a.z += v0.z; a.w += v0.w;
        b.x += v1.x; b.y += v1.y; b.z += v1.z; b.w += v1.w;
    }
    if (i < end) {
        int s0 = csr[i];
        float4 v0 = ((const float4*)feat)[(size_t)s0 * 32 + lane];
        a.x += v0.x; a.y += v0.y; a.z += v0.z; a.w += v0.w;
    }
    a.x += b.x; a.y += b.y; a.z += b.z; a.w += b.w;
    return a;
}

// ---------------------------------------------------------------------------
// tf32 tensor-core GEMM with up to 3 fused K-segments (see R4 notes).
// ---------------------------------------------------------------------------
struct Seg { const float* A; const unsigned* Wt; const float* rs; int K; };

template <int ACT>
__global__ __launch_bounds__(256, 2) void gemm_tf32(
    Seg s0, Seg s1, Seg s2, int nseg,
    const float* __restrict__ bias, float* __restrict__ C,
    float* __restrict__ C2, int M)
{
    __shared__ __align__(16) unsigned As[128][20];
    __shared__ __align__(16) unsigned Bs[128][20];
    const int tid = threadIdx.x;
    const int lane = tid & 31, warp = tid >> 5;
    const int gid = lane >> 2, q = lane & 3;
    const int wm = warp & 3, wn = warp >> 2;
    const int rowBase = blockIdx.x * 128;
    const int lrow = tid >> 2;            // 0..63
    const int lk4 = (tid & 3) * 4;        // 0,4,8,12

    float acc[2][8][4];
#pragma unroll
    for (int mt = 0; mt < 2; mt++)
#pragma unroll
        for (int nt = 0; nt < 8; nt++)
#pragma unroll
            for (int i = 0; i < 4; i++) acc[mt][nt][i] = 0.f;

    Seg segs[3] = {s0, s1, s2};
    for (int s = 0; s < nseg; s++) {
        const float* A = segs[s].A;
        const unsigned* Wt = segs[s].Wt;
        const float* rs = segs[s].rs;
        const int K = segs[s].K;
        int r0 = rowBase + lrow;      if (r0 > M - 1) r0 = M - 1;
        int r1 = rowBase + lrow + 64; if (r1 > M - 1) r1 = M - 1;
        const float sc0 = rs ? rs[r0] : 1.f;
        const float sc1 = rs ? rs[r1] : 1.f;

        for (int k0 = 0; k0 < K; k0 += 16) {
            float4 av0 = *(const float4*)&A[(size_t)r0 * K + k0 + lk4];
            float4 av1 = *(const float4*)&A[(size_t)r1 * K + k0 + lk4];
            uint4 u0 = make_uint4(f2tf(av0.x * sc0), f2tf(av0.y * sc0),
                                  f2tf(av0.z * sc0), f2tf(av0.w * sc0));
            uint4 u1 = make_uint4(f2tf(av1.x * sc1), f2tf(av1.y * sc1),
                                  f2tf(av1.z * sc1), f2tf(av1.w * sc1));
            *(uint4*)&As[lrow][lk4] = u0;
            *(uint4*)&As[lrow + 64][lk4] = u1;
            *(uint4*)&Bs[lrow][lk4]      = *(const uint4*)&Wt[(size_t)lrow * K + k0 + lk4];
            *(uint4*)&Bs[lrow + 64][lk4] = *(const uint4*)&Wt[(size_t)(lrow + 64) * K + k0 + lk4];
            __syncthreads();

#pragma unroll
            for (int kk = 0; kk < 16; kk += 8) {
                unsigned a[2][4], b[8][2];
#pragma unroll
                for (int mt = 0; mt < 2; mt++) {
                    int r = wm * 32 + mt * 16 + gid;
                    a[mt][0] = As[r][kk + q];
                    a[mt][1] = As[r + 8][kk + q];
                    a[mt][2] = As[r][kk + q + 4];
                    a[mt][3] = As[r + 8][kk + q + 4];
                }
#pragma unroll
                for (int nt = 0; nt < 8; nt++) {
                    int n = wn * 64 + nt * 8 + gid;
                    b[nt][0] = Bs[n][kk + q];
                    b[nt][1] = Bs[n][kk + q + 4];
                }
#pragma unroll
                for (int mt = 0; mt < 2; mt++)
#pragma unroll
                    for (int nt = 0; nt < 8; nt++)
                        mma_tf32(acc[mt][nt], a[mt], b[nt]);
            }
            __syncthreads();
        }
    }

    // Epilogue: bias + activation + store
#pragma unroll
    for (int mt = 0; mt < 2; mt++) {
        int row0 = rowBase + wm * 32 + mt * 16 + gid;
        int row1 = row0 + 8;
#pragma unroll
        for (int nt = 0; nt < 8; nt++) {
            int col = wn * 64 + nt * 8 + q * 2;
            float b0 = bias[col], b1 = bias[col + 1];
            float v0 = acc[mt][nt][0] + b0, v1 = acc[mt][nt][1] + b1;
            float v2 = acc[mt][nt][2] + b0, v3 = acc[mt][nt][3] + b1;
            if (ACT == 1) { v0 = lrelu(v0); v1 = lrelu(v1); v2 = lrelu(v2); v3 = lrelu(v3); }
            if (ACT == 2) {
                v0 = fmaxf(v0, 0.f); v1 = fmaxf(v1, 0.f);
                v2 = fmaxf(v2, 0.f); v3 = fmaxf(v3, 0.f);
            }
            if (row0 < M) {
                *(float2*)&C[(size_t)row0 * 128 + col] = make_float2(v0, v1);
                if (C2) *(float2*)&C2[(size_t)row0 * 128 + col] = make_float2(v0, v1);
            }
            if (row1 < M) {
                *(float2*)&C[(size_t)row1 * 128 + col] = make_float2(v2, v3);
                if (C2) *(float2*)&C2[(size_t)row1 * 128 + col] = make_float2(v2, v3);
            }
        }
    }
}

// ---------------------------------------------------------------------------
// Weight preprocessing: dst[n*K+k] = tf32(src[k*128+n] (+ src2[k*128+n]))
// ---------------------------------------------------------------------------
struct WJob { const float* src; const float* src2; unsigned* dst; int K; };
struct WJobs { WJob j[14]; };

__global__ void wprep_kernel(WJobs js) {
    WJob J = js.j[blockIdx.y];
    int idx = blockIdx.x * 256 + threadIdx.x;
    if (idx >= 128 * J.K) return;
    int n = idx / J.K, k = idx % J.K;
    float v = J.src[(size_t)k * 128 + n];
    if (J.src2) v += J.src2[(size_t)k * 128 + n];
    J.dst[idx] = f2tf(v);
}

__global__ void bcomb_kernel(const float* __restrict__ bself, const float* __restrict__ bneigh) {
    int c = threadIdx.x;  // 128
#pragma unroll
    for (int l = 0; l < 2; l++) {
        gS.b_post[l][c] = bself[(l * 3 + 0) * H + c] + bself[(l * 3 + 1) * H + c]
                        + bneigh[(l * 3 + 0) * H + c] + bneigh[(l * 3 + 1) * H + c];
        gS.b_user[l][c] = bself[(l * 3 + 2) * H + c] + bneigh[(l * 3 + 2) * H + c];
    }
}

// ---------------------------------------------------------------------------
// Fused conversation-context kernel (fp32 GEMM K=64 + row-LN + relu + scatter)
// ---------------------------------------------------------------------------
__global__ void conv_kernel(const float* __restrict__ A, const float* __restrict__ W,
                            const float* __restrict__ cvec,
                            const float* __restrict__ gw, const float* __restrict__ be,
                            const int* __restrict__ uidx, float* __restrict__ ctx, int M) {
    __shared__ float As[16][64];
    __shared__ float Ws[16][128];
    const int tid = threadIdx.x;
    const int ty = tid >> 5, tx = tid & 31;
    const int rowBase = blockIdx.x * 64;

    float acc[8][4];
#pragma unroll
    for (int r = 0; r < 8; r++)
#pragma unroll
        for (int c = 0; c < 4; c++) acc[r][c] = 0.f;

    const int arow = tid >> 2;
    const int ak = (tid & 3) * 4;
    int grow = rowBase + arow; if (grow > M - 1) grow = M - 1;

    for (int k0 = 0; k0 < 64; k0 += 16) {
        float4 av = *(const float4*)&A[(size_t)grow * 64 + k0 + ak];
        As[ak + 0][arow] = av.x;
        As[ak + 1][arow] = av.y;
        As[ak + 2][arow] = av.z;
        As[ak + 3][arow] = av.w;
#pragma unroll
        for (int t = 0; t < 2; t++) {
            int idx = tid + t * 256;
            int wk = idx >> 5, wc = (idx & 31) * 4;
            *(float4*)&Ws[wk][wc] = *(const float4*)&W[(size_t)(k0 + wk) * 128 + wc];
        }
        __syncthreads();
#pragma unroll
        for (int kk = 0; kk < 16; kk++) {
            float4 a0 = *(const float4*)&As[kk][ty * 8];
            float4 a1 = *(const float4*)&As[kk][ty * 8 + 4];
            float4 b  = *(const float4*)&Ws[kk][tx * 4];
            float ar[8] = {a0.x, a0.y, a0.z, a0.w, a1.x, a1.y, a1.z, a1.w};
#pragma unroll
            for (int r = 0; r < 8; r++) {
                acc[r][0] += ar[r] * b.x;
                acc[r][1] += ar[r] * b.y;
                acc[r][2] += ar[r] * b.z;
                acc[r][3] += ar[r] * b.w;
            }
        }
        __syncthreads();
    }

    float4 cv = ((const float4*)cvec)[tx];
    float4 gg = ((const float4*)gw)[tx];
    float4 bb = ((const float4*)be)[tx];
#pragma unroll
    for (int r = 0; r < 8; r++) {
        int row = rowBase + ty * 8 + r;
        float v0 = acc[r][0] + cv.x, v1 = acc[r][1] + cv.y;
        float v2 = acc[r][2] + cv.z, v3 = acc[r][3] + cv.w;
        float s  = warp_sum(v0 + v1 + v2 + v3);
        float ss = warp_sum(v0 * v0 + v1 * v1 + v2 * v2 + v3 * v3);
        float mean = s * (1.f / 128.f);
        float var = ss * (1.f / 128.f) - mean * mean;
        float rr = rsqrtf(var + 1e-5f);
        v0 = fmaxf((v0 - mean) * rr * gg.x + bb.x, 0.f);
        v1 = fmaxf((v1 - mean) * rr * gg.y + bb.y, 0.f);
        v2 = fmaxf((v2 - mean) * rr * gg.z + bb.z, 0.f);
        v3 = fmaxf((v3 - mean) * rr * gg.w + bb.w, 0.f);
        if (row < M) {
            int u = uidx[row];
            red4(&ctx[(size_t)u * 128 + tx * 4], make_float4(v0, v1, v2, v3));
        }
    }
}

// ---------------------------------------------------------------------------
// Counts / degrees
// ---------------------------------------------------------------------------
struct CJob { const int* idx; int n; int* cnt; };
__global__ void count6_kernel(CJob a, CJob b, CJob c, CJob d, CJob e, CJob f) {
    CJob js[6] = {a, b, c, d, e, f};
    CJob J = js[blockIdx.y];
    int i = blockIdx.x * 256 + threadIdx.x;
    if (i < J.n) atomicAdd(&J.cnt[J.idx[i]], 1);
}

__global__ void prep_user_kernel() {
    int i = blockIdx.x * blockDim.x + threadIdx.x;
    int flag = 0;
    if (i < Nu) {
        int a = gS.cnt_pub_u[i], b = gS.cnt_com_u[i];
        int c = gS.cnt_ucu_u[i], d = gS.cnt_ucu_v[i];
        gS.inv_pub_u[i] = 1.f / (float)(a > 1 ? a : 1);
        gS.inv_com_u[i] = 1.f / (float)(b > 1 ? b : 1);
        gS.inv_ucu_v[i] = 1.f / (float)(d > 1 ? d : 1);
        int deg = a + b + c + d;
        gS.deg_user[i] = deg;
        flag = deg > 0;
    }
    unsigned m = __ballot_sync(0xffffffffu, flag);
    if ((threadIdx.x & 31) == 0) atomicAdd(&gS.nz[0], __popc(m));
}

__global__ void prep_post_kernel() {
    int i = blockIdx.x * blockDim.x + threadIdx.x;
    int flag = 0;
    if (i < Np) {
        int a = gS.cnt_pub_v[i], b = gS.cnt_com_v[i];
        gS.inv_pub_v[i] = 1.f / (float)(a > 1 ? a : 1);
        gS.inv_com_v[i] = 1.f / (float)(b > 1 ? b : 1);
        int deg = a + b;
        gS.deg_post[i] = deg;
        flag = deg > 0;
    }
    unsigned m = __ballot_sync(0xffffffffu, flag);
    if ((threadIdx.x & 31) == 0) atomicAdd(&gS.nz[1], __popc(m));
}

// ---------------------------------------------------------------------------
// CSR build: exclusive scan of counts (3 kernels, 5 jobs batched) + binning
// ---------------------------------------------------------------------------
struct ScanJob { const int* cnt; int N; int* off; int* cur; };
struct ScanJobs { ScanJob j[5]; };

__global__ void scan1_kernel(ScanJobs js, int* __restrict__ bsum) {
    ScanJob J = js.j[blockIdx.y];
    int b = blockIdx.x, t = threadIdx.x;
    int C = (J.N + SCAN_G - 1) / SCAN_G;
    int tseg = (C + 255) / 256;
    int base = b * C + t * tseg;
    int endv = min(base + tseg, min((b + 1) * C, J.N));
    int tsum = 0;
    for (int i = base; i < endv; i++) tsum += J.cnt[i];
    __shared__ int s[256];
    s[t] = tsum; __syncthreads();
    for (int o = 1; o < 256; o <<= 1) {
        int v = (t >= o) ? s[t - o] : 0;
        __syncthreads(); s[t] += v; __syncthreads();
    }
    if (t == 255) bsum[blockIdx.y * SCAN_G + b] = s[255];
}

__global__ void scan2_kernel(int* __restrict__ bsum) {
    int j = blockIdx.x, t = threadIdx.x;  // 64 threads
    __shared__ int s[SCAN_G];
    int v = bsum[j * SCAN_G + t];
    s[t] = v; __syncthreads();
    for (int o = 1; o < SCAN_G; o <<= 1) {
        int x = (t >= o) ? s[t - o] : 0;
        __syncthreads(); s[t] += x; __syncthreads();
    }
    bsum[j * SCAN_G + t] = s[t] - v;  // exclusive
}

__global__ void scan3_kernel(ScanJobs js, const int* __restrict__ bsum) {
    ScanJob J = js.j[blockIdx.y];
    int b = blockIdx.x, t = threadIdx.x;
    int C = (J.N + SCAN_G - 1) / SCAN_G;
    int tseg = (C + 255) / 256;
    int base = b * C + t * tseg;
    int endv = min(base + tseg, min((b + 1) * C, J.N));
    int tsum = 0;
    for (int i = base; i < endv; i++) tsum += J.cnt[i];
    __shared__ int s[256];
    s[t] = tsum; __syncthreads();
    for (int o = 1; o < 256; o <<= 1) {
        int v = (t >= o) ? s[t - o] : 0;
        __syncthreads(); s[t] += v; __syncthreads();
    }
    int running = bsum[blockIdx.y * SCAN_G + b] + (s[t] - tsum);
    for (int i = base; i < endv; i++) {
        J.off[i] = running;
        J.cur[i] = running;
        running += J.cnt[i];
    }
    if (base < J.N && endv == J.N) J.off[J.N] = running;
}

struct BJob { const int* dst; const int* val; int n; int* cur; int* csr; };
__global__ void bin5_kernel(BJob a, BJob b, BJob c, BJob d, BJob e) {
    BJob js[5] = {a, b, c, d, e};
    BJob J = js[blockIdx.y];
    int i = blockIdx.x * 256 + threadIdx.x;
    if (i < J.n) {
        int p = atomicAdd(&J.cur[J.dst[i]], 1);
        J.csr[p] = J.val[i];
    }
}

// ---------------------------------------------------------------------------
// CSR gather kernels (replace the atomic scatters)
// ---------------------------------------------------------------------------
__global__ void gather_post_kernel(const float* __restrict__ hu) {
    int w = (blockIdx.x * 256 + threadIdx.x) >> 5;
    int lane = threadIdx.x & 31;
    if (w >= Np) return;
    float4 p = gath(gS.csr_pub_v, gS.off_pub_v[w], gS.off_pub_v[w + 1], hu, lane);
    float4 c = gath(gS.csr_com_v, gS.off_com_v[w], gS.off_com_v[w + 1], hu, lane);
    ((float4*)gS.agg_pub)[(size_t)w * 32 + lane] = p;
    ((float4*)gS.agg_com)[(size_t)w * 32 + lane] = c;
}

__global__ void gather_user_kernel(const float* __restrict__ hu) {
    int w = (blockIdx.x * 256 + threadIdx.x) >> 5;
    int lane = threadIdx.x & 31;
    if (w >= Nu) return;
    float4 a = gath(gS.csr_ucu_v, gS.off_ucu_v[w], gS.off_ucu_v[w + 1], hu, lane);
    ((float4*)gS.agg_ucu)[(size_t)w * 32 + lane] = a;
}

// ctx gather (comment/publish post means) + conv ctx + blend into h_user
__global__ void ctx_blend_kernel() {
    int u = (blockIdx.x * 256 + threadIdx.x) >> 5;
    int lane = threadIdx.x & 31;
    if (u >= Nu) return;
    float4 g1 = gath(gS.csr_com_u, gS.off_com_u[u], gS.off_com_u[u + 1], gS.post_enc, lane);
    float4 g2 = gath(gS.csr_pub_u, gS.off_pub_u[u], gS.off_pub_u[u + 1], gS.post_enc, lane);
    float s1 = 0.3f * gS.inv_com_u[u];
    float s2 = 0.5f * gS.inv_pub_u[u];
    float4 cv = ((const float4*)gS.ctx)[(size_t)u * 32 + lane];
    cv.x += s1 * g1.x + s2 * g2.x;
    cv.y += s1 * g1.y + s2 * g2.y;
    cv.z += s1 * g1.z + s2 * g2.z;
    cv.w += s1 * g1.w + s2 * g2.w;
    float4 h = ((const float4*)gS.h_user)[(size_t)u * 32 + lane];
    h.x = 0.7f * h.x + 0.3f * cv.x;
    h.y = 0.7f * h.y + 0.3f * cv.y;
    h.z = 0.7f * h.z + 0.3f * cv.z;
    h.w = 0.7f * h.w + 0.3f * cv.w;
    ((float4*)gS.h_user)[(size_t)u * 32 + lane] = h;
}

// ---------------------------------------------------------------------------
// Misc small kernels
// ---------------------------------------------------------------------------
__global__ void avgpost_kernel(const float* __restrict__ post_x) {
    int col = threadIdx.x;                 // 256 threads = 256 cols
    float s = 0.f;
    for (int r = blockIdx.x; r < Np; r += gridDim.x)
        s += post_x[(size_t)r * IN + col];
    atomicAdd(&gS.avgpost[col], s);
}

__global__ void cvec_kernel(const float* __restrict__ conv_W, const float* __restrict__ conv_b) {
    int c = threadIdx.x;                   // 128 threads
    float s = conv_b[c];
    const float scale = 1.f / (float)Np;
    for (int k = 0; k < IN; k++)
        s += gS.avgpost[k] * scale * conv_W[(size_t)(EF + k) * H + c];
    gS.cvec[c] = s;
}

// Column sums over rows with deg>0
__global__ void colsum_kernel(const float* __restrict__ buf, const int* __restrict__ deg,
                              int Nr, float* __restrict__ gm) {
    __shared__ float s[128];
    if (threadIdx.x < 128) s[threadIdx.x] = 0.f;
    __syncthreads();
    int col = threadIdx.x & 127, sub = threadIdx.x >> 7;
    float local = 0.f;
    for (int r = blockIdx.x * 2 + sub; r < Nr; r += gridDim.x * 2)
        if (deg[r] > 0) local += buf[(size_t)r * 128 + col];
    atomicAdd(&s[col], local);
    __syncthreads();
    if (threadIdx.x < 128) atomicAdd(&gm[threadIdx.x], s[threadIdx.x]);
}

// fix_zero_degree + LayerNorm (+ optional leaky relu). One warp per row.
template <bool LRELU>
__global__ void fix_ln_kernel(const float* __restrict__ hn, const float* __restrict__ init,
                              const int* __restrict__ deg, const float* __restrict__ gm,
                              const int* __restrict__ nzp,
                              const float* __restrict__ g, const float* __restrict__ b,
                              int Nr, float* __restrict__ out) {
    int w = (blockIdx.x * blockDim.x + threadIdx.x) >> 5;
    int lane = threadIdx.x & 31;
    if (w >= Nr) return;
    float4 v;
    if (deg[w] == 0) {
        float nz = fmaxf((float)(*nzp), 1.f);
        float4 e = ((const float4*)init)[(size_t)w * 32 + lane];
        float4 gv = ((const float4*)gm)[lane];
        v.x = 0.9f * e.x + 0.1f * gv.x / nz;
        v.y = 0.9f * e.y + 0.1f * gv.y / nz;
        v.z = 0.9f * e.z + 0.1f * gv.z / nz;
        v.w = 0.9f * e.w + 0.1f * gv.w / nz;
    } else {
        v = ((const float4*)hn)[(size_t)w * 32 + lane];
    }
    float s  = warp_sum(v.x + v.y + v.z + v.w);
    float ss = warp_sum(v.x * v.x + v.y * v.y + v.z * v.z + v.w * v.w);
    float mean = s * (1.f / 128.f);
    float var = ss * (1.f / 128.f) - mean * mean;
    float r = rsqrtf(var + 1e-5f);
    float4 gg = ((const float4*)g)[lane], bb = ((const float4*)b)[lane];
    v.x = (v.x - mean) * r * gg.x + bb.x;
    v.y = (v.y - mean) * r * gg.y + bb.y;
    v.z = (v.z - mean) * r * gg.z + bb.z;
    v.w = (v.w - mean) * r * gg.w + bb.w;
    if (LRELU) { v.x = lrelu(v.x); v.y = lrelu(v.y); v.z = lrelu(v.z); v.w = lrelu(v.w); }
    ((float4*)out)[(size_t)w * 32 + lane] = v;
}

// Final tiny GEMM: out[Nu,4] = T[Nu,128] @ W2[128,4] + b2. One warp per row.
__global__ void cls2_kernel(const float* __restrict__ T, const float* __restrict__ W2,
                            const float* __restrict__ b2, float* __restrict__ out, int Nr) {
    int w = (blockIdx.x * blockDim.x + threadIdx.x) >> 5;
    int lane = threadIdx.x & 31;
    if (w >= Nr) return;
    float4 t = ((const float4*)T)[(size_t)w * 32 + lane];
    float tv[4] = {t.x, t.y, t.z, t.w};
    float a0 = 0.f, a1 = 0.f, a2 = 0.f, a3 = 0.f;
    const float4* W4 = (const float4*)W2;  // row k of [128][4] = one float4
#pragma unroll
    for (int j = 0; j < 4; j++) {
        float4 wr = W4[lane * 4 + j];
        a0 += tv[j] * wr.x; a1 += tv[j] * wr.y; a2 += tv[j] * wr.z; a3 += tv[j] * wr.w;
    }
    a0 = warp_sum(a0); a1 = warp_sum(a1); a2 = warp_sum(a2); a3 = warp_sum(a3);
    if (lane == 0) {
        out[(size_t)w * 4 + 0] = a0 + b2[0];
        out[(size_t)w * 4 + 1] = a1 + b2[1];
        out[(size_t)w * 4 + 2] = a2 + b2[2];
        out[(size_t)w * 4 + 3] = a3 + b2[3];
    }
}

// ---------------------------------------------------------------------------
// Host orchestration
// ---------------------------------------------------------------------------
extern "C" void kernel_launch(void* const* d_in, const int* in_sizes, int n_in,
                              void* d_out, int out_size) {
    const float* user_x      = (const float*)d_in[0];
    const float* post_x      = (const float*)d_in[1];
    const float* parent_feat = (const float*)d_in[2];
    const float* user_proj_W = (const float*)d_in[3];
    const float* user_proj_b = (const float*)d_in[4];
    const float* post_proj_W = (const float*)d_in[5];
    const float* post_proj_b = (const float*)d_in[6];
    const float* conv_W      = (const float*)d_in[7];
    const float* conv_b      = (const float*)d_in[8];
    const float* conv_g      = (const float*)d_in[9];
    const float* conv_beta   = (const float*)d_in[10];
    const float* uce_W       = (const float*)d_in[11];
    const float* uce_b       = (const float*)d_in[12];
    const float* Wself       = (const float*)d_in[13];
    const float* bself       = (const float*)d_in[14];
    const float* Wneigh      = (const float*)d_in[15];
    const float* bneigh      = (const float*)d_in[16];
    const float* ln_user_g   = (const float*)d_in[17];
    const float* ln_user_b   = (const float*)d_in[18];
    const float* ln_post_g   = (const float*)d_in[19];
    const float* ln_post_b   = (const float*)d_in[20];
    const float* cls_W1      = (const float*)d_in[21];
    const float* cls_b1      = (const float*)d_in[22];
    const float* cls_W2      = (const float*)d_in[23];
    const float* cls_b2      = (const float*)d_in[24];
    const int* publish_u     = (const int*)d_in[25];
    const int* publish_v     = (const int*)d_in[26];
    const int* comment_u     = (const int*)d_in[27];
    const int* comment_v     = (const int*)d_in[28];
    const int* ucu_u         = (const int*)d_in[29];
    const int* ucu_v         = (const int*)d_in[30];
    float* out = (float*)d_out;

    Scratch* S = nullptr;
    cudaGetSymbolAddress((void**)&S, gS);

    // --- zero per-launch accumulators ---------------------------------------
    cudaMemsetAsync(S->cnt_pub_u, 0, sizeof(int) * (size_t)(4 * Nu + 2 * Np), 0);
    cudaMemsetAsync(S->nz, 0, sizeof(int) * 4, 0);
    cudaMemsetAsync(S->avgpost, 0, sizeof(float) * IN, 0);
    cudaMemsetAsync(S->ctx, 0, sizeof(float) * (size_t)Nu * H, 0);

    // --- counts / degrees ----------------------------------------------------
    {
        CJob c0 = {publish_u, Ep, S->cnt_pub_u};
        CJob c1 = {publish_v, Ep, S->cnt_pub_v};
        CJob c2 = {comment_u, Ec, S->cnt_com_u};
        CJob c3 = {comment_v, Ec, S->cnt_com_v};
        CJob c4 = {ucu_u, Eu, S->cnt_ucu_u};
        CJob c5 = {ucu_v, Eu, S->cnt_ucu_v};
        dim3 g((Ec + 255) / 256, 6);
        count6_kernel<<<g, 256>>>(c0, c1, c2, c3, c4, c5);
    }
    prep_user_kernel<<<(Nu + 255) / 256, 256>>>();
    prep_post_kernel<<<(Np + 255) / 256, 256>>>();

    // --- CSR build (scan + bin) ----------------------------------------------
    {
        ScanJobs sj;
        sj.j[0] = {S->cnt_pub_v, Np, S->off_pub_v, S->cur_pub_v};
        sj.j[1] = {S->cnt_com_v, Np, S->off_com_v, S->cur_com_v};
        sj.j[2] = {S->cnt_ucu_v, Nu, S->off_ucu_v, S->cur_ucu_v};
        sj.j[3] = {S->cnt_com_u, Nu, S->off_com_u, S->cur_com_u};
        sj.j[4] = {S->cnt_pub_u, Nu, S->off_pub_u, S->cur_pub_u};
        dim3 g1(SCAN_G, 5);
        scan1_kernel<<<g1, 256>>>(sj, S->blocksums);
        scan2_kernel<<<5, SCAN_G>>>(S->blocksums);
        scan3_kernel<<<g1, 256>>>(sj, S->blocksums);

        BJob b0 = {publish_v, publish_u, Ep, S->cur_pub_v, S->csr_pub_v};
        BJob b1 = {comment_v, comment_u, Ec, S->cur_com_v, S->csr_com_v};
        BJob b2 = {ucu_v, ucu_u, Eu, S->cur_ucu_v, S->csr_ucu_v};
        BJob b3 = {comment_u, comment_v, Ec, S->cur_com_u, S->csr_com_u};
        BJob b4 = {publish_u, publish_v, Ep, S->cur_pub_u, S->csr_pub_u};
        dim3 gb((Ec + 255) / 256, 5);
        bin5_kernel<<<gb, 256>>>(b0, b1, b2, b3, b4);
    }

    // --- constants -----------------------------------------------------------
    avgpost_kernel<<<512, 256>>>(post_x);
    cvec_kernel<<<1, 128>>>(conv_W, conv_b);

    // --- weight preprocessing (transpose + tf32) -----------------------------
    {
        WJobs js;
        js.j[0] = {user_proj_W, nullptr, S->Wt_up, 256};
        js.j[1] = {post_proj_W, nullptr, S->Wt_pp, 256};
        js.j[2] = {uce_W, nullptr, S->Wt_uce, 256};
        js.j[3] = {cls_W1, nullptr, S->Wt_cls, 128};
        for (int l = 0; l < 2; l++) {
            js.j[4 + 5 * l + 0] = {Wself + (size_t)(l * 3 + 0) * HH, Wself + (size_t)(l * 3 + 1) * HH, S->Wt_ss[l], 128};
            js.j[4 + 5 * l + 1] = {Wneigh + (size_t)(l * 3 + 0) * HH, nullptr, S->Wt_n0[l], 128};
            js.j[4 + 5 * l + 2] = {Wneigh + (size_t)(l * 3 + 1) * HH, nullptr, S->Wt_n1[l], 128};
            js.j[4 + 5 * l + 3] = {Wself + (size_t)(l * 3 + 2) * HH, nullptr, S->Wt_s2[l], 128};
            js.j[4 + 5 * l + 4] = {Wneigh + (size_t)(l * 3 + 2) * HH, nullptr, S->Wt_n2[l], 128};
        }
        dim3 g(128, 14);
        wprep_kernel<<<g, 256>>>(js);
    }
    bcomb_kernel<<<1, 128>>>(bself, bneigh);

    Seg z = {nullptr, nullptr, nullptr, 0};

    // --- input projections (tf32); init copies fused into epilogue -----------
    {
        Seg s = {user_x, S->Wt_up, nullptr, 256};
        gemm_tf32<1><<<(Nu + 127) / 128, 256>>>(s, z, z, 1, user_proj_b, S->h_user, S->init_user, Nu);
    }
    {
        Seg s = {post_x, S->Wt_pp, nullptr, 256};
        gemm_tf32<1><<<(Np + 127) / 128, 256>>>(s, z, z, 1, post_proj_b, S->h_post, S->init_post, Np);
    }
    {
        Seg s = {post_x, S->Wt_uce, nullptr, 256};
        gemm_tf32<2><<<(Np + 127) / 128, 256>>>(s, z, z, 1, uce_b, S->post_enc, nullptr, Np);
    }

    // --- ctx: conv edge-GEMM scatter + CSR gathers + blend --------------------
    conv_kernel<<<(Eu + 63) / 64, 256>>>(parent_feat, conv_W, S->cvec, conv_g, conv_beta, ucu_u, S->ctx, Eu);
    ctx_blend_kernel<<<((size_t)Nu * 32 + 255) / 256, 256>>>();

    // --- SAGE layers ----------------------------------------------------------
    for (int l = 0; l < 2; l++) {
        gather_post_kernel<<<((size_t)Np * 32 + 255) / 256, 256>>>(S->h_user);
        gather_user_kernel<<<((size_t)Nu * 32 + 255) / 256, 256>>>(S->h_user);

        // post_new = h_post@(Ws0+Ws1) + mean_pub@Wn0 + mean_com@Wn1 + b_post[l]
        {
            Seg sA = {S->h_post, S->Wt_ss[l], nullptr, 128};
            Seg sB = {S->agg_pub, S->Wt_n0[l], S->inv_pub_v, 128};
            Seg sC = {S->agg_com, S->Wt_n1[l], S->inv_com_v, 128};
            gemm_tf32<0><<<(Np + 127) / 128, 256>>>(sA, sB, sC, 3, S->b_post[l], S->post_new, nullptr, Np);
        }
        // user_new = h_user@Ws2 + mean_ucu@Wn2 + b_user[l]
        {
            Seg sA = {S->h_user, S->Wt_s2[l], nullptr, 128};
            Seg sB = {S->agg_ucu, S->Wt_n2[l], S->inv_ucu_v, 128};
            gemm_tf32<0><<<(Nu + 127) / 128, 256>>>(sA, sB, z, 2, S->b_user[l], S->user_new, nullptr, Nu);
        }

        cudaMemsetAsync(S->gm_user, 0, sizeof(float) * 2 * H, 0);  // gm_user + gm_post
        colsum_kernel<<<512, 256>>>(S->user_new, S->deg_user, Nu, S->gm_user);
        colsum_kernel<<<512, 256>>>(S->post_new, S->deg_post, Np, S->gm_post);
        if (l == 0) {
            fix_ln_kernel<true><<<((size_t)Nu * 32 + 255) / 256, 256>>>(S->user_new, S->init_user, S->deg_user, S->gm_user, &S->nz[0], ln_user_g, ln_user_b, Nu, S->h_user);
            fix_ln_kernel<true><<<((size_t)Np * 32 + 255) / 256, 256>>>(S->post_new, S->init_post, S->deg_post, S->gm_post, &S->nz[1], ln_post_g, ln_post_b, Np, S->h_post);
        } else {
            fix_ln_kernel<false><<<((size_t)Nu * 32 + 255) / 256, 256>>>(S->user_new, S->init_user, S->deg_user, S->gm_user, &S->nz[0], ln_user_g, ln_user_b, Nu, S->h_user);
            fix_ln_kernel<false><<<((size_t)Np * 32 + 255) / 256, 256>>>(S->post_new, S->init_post, S->deg_post, S->gm_post, &S->nz[1], ln_post_g, ln_post_b, Np, S->h_post);
        }
    }

    // --- classifier -----------------------------------------------------------
    {
        Seg s = {S->h_user, S->Wt_cls, nullptr, 128};
        gemm_tf32<1><<<(Nu + 127) / 128, 256>>>(s, z, z, 1, cls_b1, S->user_new, nullptr, Nu);
    }
    cls2_kernel<<<((size_t)Nu * 32 + 255) / 256, 256>>>(S->user_new, cls_W2, cls_b2, out, Nu);
}

// round 10
// speedup vs baseline: 1.4677x; 1.0649x over previous
#include <cuda_runtime.h>

// ---------------------------------------------------------------------------
// Problem constants
// ---------------------------------------------------------------------------
constexpr int Nu = 50000, Np = 20000, IN = 256, EF = 64, H = 128;
constexpr int Ep = 200000, Ec = 800000, Eu = 300000;
constexpr int HH = H * H;
constexpr int SCAN_G = 64;

// ---------------------------------------------------------------------------
// Scratch (device global; allocation-free contract)
// ---------------------------------------------------------------------------
struct alignas(16) Scratch {
    float h_user[(size_t)Nu * H];
    float init_user[(size_t)Nu * H];
    float ctx[(size_t)Nu * H];
    float user_new[(size_t)Nu * H];   // also reused as classifier tmp
    float agg_ucu[(size_t)Nu * H];
    float h_post[(size_t)Np * H];
    float init_post[(size_t)Np * H];
    float post_enc[(size_t)Np * H];
    float post_new[(size_t)Np * H];
    float agg_pub[(size_t)Np * H];
    float agg_com[(size_t)Np * H];
    int cnt_pub_u[Nu]; int cnt_com_u[Nu]; int cnt_ucu_u[Nu]; int cnt_ucu_v[Nu];
    int cnt_pub_v[Np]; int cnt_com_v[Np];
    float inv_pub_u[Nu]; float inv_com_u[Nu]; float inv_ucu_v[Nu];
    float inv_pub_v[Np]; float inv_com_v[Np];
    int deg_user[Nu]; int deg_post[Np];
    float avgpost[IN];
    float cvec[H];
    float gm_user[H]; float gm_post[H];   // contiguous: single memset
    int nz[4];                            // padded so next member is 16B-aligned
    // CSR structures (built once per launch)
    int off_pub_v[Np + 1]; int off_com_v[Np + 1]; int off_ucu_v[Nu + 1];
    int off_com_u[Nu + 1]; int off_pub_u[Nu + 1];
    int cur_pub_v[Np]; int cur_com_v[Np]; int cur_ucu_v[Nu];
    int cur_com_u[Nu]; int cur_pub_u[Nu];
    int blocksums[5 * SCAN_G];
    int csr_pub_v[Ep]; int csr_com_v[Ec]; int csr_ucu_v[Eu];
    int csr_com_u[Ec]; int csr_pub_u[Ep];
    // tf32-converted, n-major (Wt[n][k]) weights. 16B alignment REQUIRED for
    // the uint4 loads in the mma kernels (R3 misaligned-address crash).
    alignas(16) unsigned Wt_up[128 * 256];
    alignas(16) unsigned Wt_pp[128 * 256];
    alignas(16) unsigned Wt_uce[128 * 256];
    alignas(16) unsigned Wt_cls[128 * 128];
    alignas(16) unsigned Wt_conv[128 * 64];
    alignas(16) unsigned Wt_ss[2][HH];   // Wself(l,0)+Wself(l,1)
    alignas(16) unsigned Wt_n0[2][HH];
    alignas(16) unsigned Wt_n1[2][HH];
    alignas(16) unsigned Wt_s2[2][HH];
    alignas(16) unsigned Wt_n2[2][HH];
    float b_post[2][H]; float b_user[2][H];
};
__device__ Scratch gS;

// ---------------------------------------------------------------------------
// Helpers
// ---------------------------------------------------------------------------
__device__ __forceinline__ float warp_sum(float v) {
#pragma unroll
    for (int o = 16; o; o >>= 1) v += __shfl_xor_sync(0xffffffffu, v, o);
    return v;
}

__device__ __forceinline__ void red2(float* p, float a, float b) {
    asm volatile("red.global.add.v2.f32 [%0], {%1,%2};"
                 :: "l"(p), "f"(a), "f"(b) : "memory");
}

__device__ __forceinline__ float lrelu(float x) { return x >= 0.f ? x : 0.01f * x; }

__device__ __forceinline__ unsigned f2tf(float x) {
    unsigned r;
    asm("cvt.rna.tf32.f32 %0, %1;" : "=r"(r) : "f"(x));
    return r;
}

__device__ __forceinline__ void mma_tf32(float c[4], const unsigned a[4], const unsigned b[2]) {
    asm volatile(
        "mma.sync.aligned.m16n8k8.row.col.f32.tf32.tf32.f32 "
        "{%0,%1,%2,%3},{%4,%5,%6,%7},{%8,%9},{%0,%1,%2,%3};"
        : "+f"(c[0]), "+f"(c[1]), "+f"(c[2]), "+f"(c[3])
        : "r"(a[0]), "r"(a[1]), "r"(a[2]), "r"(a[3]), "r"(b[0]), "r"(b[1]));
}

// Gather-sum a 512B feature row range via CSR (dual accumulator for MLP=2).
__device__ __forceinline__ float4 gath(const int* __restrict__ csr, int beg, int end,
                                       const float* __restrict__ feat, int lane) {
    float4 a = make_float4(0.f, 0.f, 0.f, 0.f);
    float4 b = make_float4(0.f, 0.f, 0.f, 0.f);
    int i = beg;
    for (; i + 1 < end; i += 2) {
        int s0 = csr[i], s1 = csr[i + 1];
        float4 v0 = ((const float4*)feat)[(size_t)s0 * 32 + lane];
        float4 v1 = ((const float4*)feat)[(size_t)s1 * 32 + lane];
        a.x += v0.x; a.y += v0.y; a.z += v0.z; a.w += v0.w;
        b.x += v1.x; b.y += v1.y; b.z += v1.z; b.w += v1.w;
    }
    if (i < end) {
        int s0 = csr[i];
        float4 v0 = ((const float4*)feat)[(size_t)s0 * 32 + lane];
        a.x += v0.x; a.y += v0.y; a.z += v0.z; a.w += v0.w;
    }
    a.x += b.x; a.y += b.y; a.z += b.z; a.w += b.w;
    return a;
}

// ---------------------------------------------------------------------------
// tf32 tensor-core GEMM with up to 3 fused K-segments (see R4 notes).
// ---------------------------------------------------------------------------
struct Seg { const float* A; const unsigned* Wt; const float* rs; int K; };

template <int ACT>
__global__ __launch_bounds__(256, 2) void gemm_tf32(
    Seg s0, Seg s1, Seg s2, int nseg,
    const float* __restrict__ bias, float* __restrict__ C,
    float* __restrict__ C2, int M)
{
    __shared__ __align__(16) unsigned As[128][20];
    __shared__ __align__(16) unsigned Bs[128][20];
    const int tid = threadIdx.x;
    const int lane = tid & 31, warp = tid >> 5;
    const int gid = lane >> 2, q = lane & 3;
    const int wm = warp & 3, wn = warp >> 2;
    const int rowBase = blockIdx.x * 128;
    const int lrow = tid >> 2;            // 0..63
    const int lk4 = (tid & 3) * 4;        // 0,4,8,12

    float acc[2][8][4];
#pragma unroll
    for (int mt = 0; mt < 2; mt++)
#pragma unroll
        for (int nt = 0; nt < 8; nt++)
#pragma unroll
            for (int i = 0; i < 4; i++) acc[mt][nt][i] = 0.f;

    Seg segs[3] = {s0, s1, s2};
    for (int s = 0; s < nseg; s++) {
        const float* A = segs[s].A;
        const unsigned* Wt = segs[s].Wt;
        const float* rs = segs[s].rs;
        const int K = segs[s].K;
        int r0 = rowBase + lrow;      if (r0 > M - 1) r0 = M - 1;
        int r1 = rowBase + lrow + 64; if (r1 > M - 1) r1 = M - 1;
        const float sc0 = rs ? rs[r0] : 1.f;
        const float sc1 = rs ? rs[r1] : 1.f;

        for (int k0 = 0; k0 < K; k0 += 16) {
            float4 av0 = *(const float4*)&A[(size_t)r0 * K + k0 + lk4];
            float4 av1 = *(const float4*)&A[(size_t)r1 * K + k0 + lk4];
            uint4 u0 = make_uint4(f2tf(av0.x * sc0), f2tf(av0.y * sc0),
                                  f2tf(av0.z * sc0), f2tf(av0.w * sc0));
            uint4 u1 = make_uint4(f2tf(av1.x * sc1), f2tf(av1.y * sc1),
                                  f2tf(av1.z * sc1), f2tf(av1.w * sc1));
            *(uint4*)&As[lrow][lk4] = u0;
            *(uint4*)&As[lrow + 64][lk4] = u1;
            *(uint4*)&Bs[lrow][lk4]      = *(const uint4*)&Wt[(size_t)lrow * K + k0 + lk4];
            *(uint4*)&Bs[lrow + 64][lk4] = *(const uint4*)&Wt[(size_t)(lrow + 64) * K + k0 + lk4];
            __syncthreads();

#pragma unroll
            for (int kk = 0; kk < 16; kk += 8) {
                unsigned a[2][4], b[8][2];
#pragma unroll
                for (int mt = 0; mt < 2; mt++) {
                    int r = wm * 32 + mt * 16 + gid;
                    a[mt][0] = As[r][kk + q];
                    a[mt][1] = As[r + 8][kk + q];
                    a[mt][2] = As[r][kk + q + 4];
                    a[mt][3] = As[r + 8][kk + q + 4];
                }
#pragma unroll
                for (int nt = 0; nt < 8; nt++) {
                    int n = wn * 64 + nt * 8 + gid;
                    b[nt][0] = Bs[n][kk + q];
                    b[nt][1] = Bs[n][kk + q + 4];
                }
#pragma unroll
                for (int mt = 0; mt < 2; mt++)
#pragma unroll
                    for (int nt = 0; nt < 8; nt++)
                        mma_tf32(acc[mt][nt], a[mt], b[nt]);
            }
            __syncthreads();
        }
    }

    // Epilogue: bias + activation + store
#pragma unroll
    for (int mt = 0; mt < 2; mt++) {
        int row0 = rowBase + wm * 32 + mt * 16 + gid;
        int row1 = row0 + 8;
#pragma unroll
        for (int nt = 0; nt < 8; nt++) {
            int col = wn * 64 + nt * 8 + q * 2;
            float b0 = bias[col], b1 = bias[col + 1];
            float v0 = acc[mt][nt][0] + b0, v1 = acc[mt][nt][1] + b1;
            float v2 = acc[mt][nt][2] + b0, v3 = acc[mt][nt][3] + b1;
            if (ACT == 1) { v0 = lrelu(v0); v1 = lrelu(v1); v2 = lrelu(v2); v3 = lrelu(v3); }
            if (ACT == 2) {
                v0 = fmaxf(v0, 0.f); v1 = fmaxf(v1, 0.f);
                v2 = fmaxf(v2, 0.f); v3 = fmaxf(v3, 0.f);
            }
            if (row0 < M) {
                *(float2*)&C[(size_t)row0 * 128 + col] = make_float2(v0, v1);
                if (C2) *(float2*)&C2[(size_t)row0 * 128 + col] = make_float2(v0, v1);
            }
            if (row1 < M) {
                *(float2*)&C[(size_t)row1 * 128 + col] = make_float2(v2, v3);
                if (C2) *(float2*)&C2[(size_t)row1 * 128 + col] = make_float2(v2, v3);
            }
        }
    }
}

// ---------------------------------------------------------------------------
// conv via tensor cores: per-edge cc = relu(LN(parent_feat@convW + cvec)),
// then ctx[ucu_u[e]] += cc. BM=128 edges, N=128, K=64.
// Row-LN: per-thread partials -> shfl over q-quad -> smem atomics across the
// two wn-half warps -> normalize in-fragment -> red.v2 scatter.
// ---------------------------------------------------------------------------
__global__ __launch_bounds__(256, 2) void conv_mma_kernel(
    const float* __restrict__ A, const unsigned* __restrict__ Wt,
    const float* __restrict__ cvec, const float* __restrict__ gw,
    const float* __restrict__ be, const int* __restrict__ uidx,
    float* __restrict__ ctx, int M)
{
    __shared__ __align__(16) unsigned As[128][20];
    __shared__ __align__(16) unsigned Bs[128][20];
    __shared__ float rsum[128], rssq[128];
    const int tid = threadIdx.x;
    const int lane = tid & 31, warp = tid >> 5;
    const int gid = lane >> 2, q = lane & 3;
    const int wm = warp & 3, wn = warp >> 2;
    const int rowBase = blockIdx.x * 128;
    const int lrow = tid >> 2;
    const int lk4 = (tid & 3) * 4;

    float acc[2][8][4];
#pragma unroll
    for (int mt = 0; mt < 2; mt++)
#pragma unroll
        for (int nt = 0; nt < 8; nt++)
#pragma unroll
            for (int i = 0; i < 4; i++) acc[mt][nt][i] = 0.f;

    int r0 = rowBase + lrow;      if (r0 > M - 1) r0 = M - 1;
    int r1 = rowBase + lrow + 64; if (r1 > M - 1) r1 = M - 1;

    if (tid < 128) { rsum[tid] = 0.f; rssq[tid] = 0.f; }

    for (int k0 = 0; k0 < 64; k0 += 16) {
        float4 av0 = *(const float4*)&A[(size_t)r0 * 64 + k0 + lk4];
        float4 av1 = *(const float4*)&A[(size_t)r1 * 64 + k0 + lk4];
        *(uint4*)&As[lrow][lk4] = make_uint4(f2tf(av0.x), f2tf(av0.y), f2tf(av0.z), f2tf(av0.w));
        *(uint4*)&As[lrow + 64][lk4] = make_uint4(f2tf(av1.x), f2tf(av1.y), f2tf(av1.z), f2tf(av1.w));
        *(uint4*)&Bs[lrow][lk4]      = *(const uint4*)&Wt[(size_t)lrow * 64 + k0 + lk4];
        *(uint4*)&Bs[lrow + 64][lk4] = *(const uint4*)&Wt[(size_t)(lrow + 64) * 64 + k0 + lk4];
        __syncthreads();
#pragma unroll
        for (int kk = 0; kk < 16; kk += 8) {
            unsigned a[2][4], b[8][2];
#pragma unroll
            for (int mt = 0; mt < 2; mt++) {
                int r = wm * 32 + mt * 16 + gid;
                a[mt][0] = As[r][kk + q];
                a[mt][1] = As[r + 8][kk + q];
                a[mt][2] = As[r][kk + q + 4];
                a[mt][3] = As[r + 8][kk + q + 4];
            }
#pragma unroll
            for (int nt = 0; nt < 8; nt++) {
                int n = wn * 64 + nt * 8 + gid;
                b[nt][0] = Bs[n][kk + q];
                b[nt][1] = Bs[n][kk + q + 4];
            }
#pragma unroll
            for (int mt = 0; mt < 2; mt++)
#pragma unroll
                for (int nt = 0; nt < 8; nt++)
                    mma_tf32(acc[mt][nt], a[mt], b[nt]);
        }
        __syncthreads();
    }

    // add cvec; per-row partial sums (row0 uses c0,c1; row1=row0+8 uses c2,c3)
#pragma unroll
    for (int mt = 0; mt < 2; mt++) {
        float ps0 = 0.f, pq0 = 0.f, ps1 = 0.f, pq1 = 0.f;
#pragma unroll
        for (int nt = 0; nt < 8; nt++) {
            int col = wn * 64 + nt * 8 + q * 2;
            float cv0 = cvec[col], cv1 = cvec[col + 1];
            acc[mt][nt][0] += cv0; acc[mt][nt][1] += cv1;
            acc[mt][nt][2] += cv0; acc[mt][nt][3] += cv1;
            ps0 += acc[mt][nt][0] + acc[mt][nt][1];
            pq0 += acc[mt][nt][0] * acc[mt][nt][0] + acc[mt][nt][1] * acc[mt][nt][1];
            ps1 += acc[mt][nt][2] + acc[mt][nt][3];
            pq1 += acc[mt][nt][2] * acc[mt][nt][2] + acc[mt][nt][3] * acc[mt][nt][3];
        }
#pragma unroll
        for (int o = 1; o <= 2; o <<= 1) {
            ps0 += __shfl_xor_sync(0xffffffffu, ps0, o);
            pq0 += __shfl_xor_sync(0xffffffffu, pq0, o);
            ps1 += __shfl_xor_sync(0xffffffffu, ps1, o);
            pq1 += __shfl_xor_sync(0xffffffffu, pq1, o);
        }
        if (q == 0) {
            int rl = wm * 32 + mt * 16 + gid;
            atomicAdd(&rsum[rl], ps0); atomicAdd(&rssq[rl], pq0);
            atomicAdd(&rsum[rl + 8], ps1); atomicAdd(&rssq[rl + 8], pq1);
        }
    }
    __syncthreads();

    // normalize + relu + scatter
#pragma unroll
    for (int mt = 0; mt < 2; mt++) {
        int rl = wm * 32 + mt * 16 + gid;
        int row0 = rowBase + rl, row1 = row0 + 8;
        float m0 = rsum[rl] * (1.f / 128.f);
        float v0 = rssq[rl] * (1.f / 128.f) - m0 * m0;
        float rr0 = rsqrtf(v0 + 1e-5f);
        float m1 = rsum[rl + 8] * (1.f / 128.f);
        float v1 = rssq[rl + 8] * (1.f / 128.f) - m1 * m1;
        float rr1 = rsqrtf(v1 + 1e-5f);
        int u0 = (row0 < M) ? uidx[row0] : -1;
        int u1 = (row1 < M) ? uidx[row1] : -1;
#pragma unroll
        for (int nt = 0; nt < 8; nt++) {
            int col = wn * 64 + nt * 8 + q * 2;
            float g0 = gw[col], g1 = gw[col + 1];
            float b0 = be[col], b1 = be[col + 1];
            if (u0 >= 0) {
                float x0 = fmaxf((acc[mt][nt][0] - m0) * rr0 * g0 + b0, 0.f);
                float x1 = fmaxf((acc[mt][nt][1] - m0) * rr0 * g1 + b1, 0.f);
                red2(&ctx[(size_t)u0 * 128 + col], x0, x1);
            }
            if (u1 >= 0) {
                float x2 = fmaxf((acc[mt][nt][2] - m1) * rr1 * g0 + b0, 0.f);
                float x3 = fmaxf((acc[mt][nt][3] - m1) * rr1 * g1 + b1, 0.f);
                red2(&ctx[(size_t)u1 * 128 + col], x2, x3);
            }
        }
    }
}

// ---------------------------------------------------------------------------
// Weight preprocessing: dst[n*K+k] = tf32(src[k*128+n] (+ src2[k*128+n]))
// ---------------------------------------------------------------------------
struct WJob { const float* src; const float* src2; unsigned* dst; int K; };
struct WJobs { WJob j[15]; };

__global__ void wprep_kernel(WJobs js) {
    WJob J = js.j[blockIdx.y];
    int idx = blockIdx.x * 256 + threadIdx.x;
    if (idx >= 128 * J.K) return;
    int n = idx / J.K, k = idx % J.K;
    float v = J.src[(size_t)k * 128 + n];
    if (J.src2) v += J.src2[(size_t)k * 128 + n];
    J.dst[idx] = f2tf(v);
}

__global__ void bcomb_kernel(const float* __restrict__ bself, const float* __restrict__ bneigh) {
    int c = threadIdx.x;  // 128
#pragma unroll
    for (int l = 0; l < 2; l++) {
        gS.b_post[l][c] = bself[(l * 3 + 0) * H + c] + bself[(l * 3 + 1) * H + c]
                        + bneigh[(l * 3 + 0) * H + c] + bneigh[(l * 3 + 1) * H + c];
        gS.b_user[l][c] = bself[(l * 3 + 2) * H + c] + bneigh[(l * 3 + 2) * H + c];
    }
}

// ---------------------------------------------------------------------------
// Counts / degrees
// ---------------------------------------------------------------------------
struct CJob { const int* idx; int n; int* cnt; };
__global__ void count6_kernel(CJob a, CJob b, CJob c, CJob d, CJob e, CJob f) {
    CJob js[6] = {a, b, c, d, e, f};
    CJob J = js[blockIdx.y];
    int i = blockIdx.x * 256 + threadIdx.x;
    if (i < J.n) atomicAdd(&J.cnt[J.idx[i]], 1);
}

__global__ void prep_user_kernel() {
    int i = blockIdx.x * blockDim.x + threadIdx.x;
    int flag = 0;
    if (i < Nu) {
        int a = gS.cnt_pub_u[i], b = gS.cnt_com_u[i];
        int c = gS.cnt_ucu_u[i], d = gS.cnt_ucu_v[i];
        gS.inv_pub_u[i] = 1.f / (float)(a > 1 ? a : 1);
        gS.inv_com_u[i] = 1.f / (float)(b > 1 ? b : 1);
        gS.inv_ucu_v[i] = 1.f / (float)(d > 1 ? d : 1);
        int deg = a + b + c + d;
        gS.deg_user[i] = deg;
        flag = deg > 0;
    }
    unsigned m = __ballot_sync(0xffffffffu, flag);
    if ((threadIdx.x & 31) == 0) atomicAdd(&gS.nz[0], __popc(m));
}

__global__ void prep_post_kernel() {
    int i = blockIdx.x * blockDim.x + threadIdx.x;
    int flag = 0;
    if (i < Np) {
        int a = gS.cnt_pub_v[i], b = gS.cnt_com_v[i];
        gS.inv_pub_v[i] = 1.f / (float)(a > 1 ? a : 1);
        gS.inv_com_v[i] = 1.f / (float)(b > 1 ? b : 1);
        int deg = a + b;
        gS.deg_post[i] = deg;
        flag = deg > 0;
    }
    unsigned m = __ballot_sync(0xffffffffu, flag);
    if ((threadIdx.x & 31) == 0) atomicAdd(&gS.nz[1], __popc(m));
}

// ---------------------------------------------------------------------------
// CSR build: exclusive scan of counts (3 kernels, 5 jobs batched) + binning
// ---------------------------------------------------------------------------
struct ScanJob { const int* cnt; int N; int* off; int* cur; };
struct ScanJobs { ScanJob j[5]; };

__global__ void scan1_kernel(ScanJobs js, int* __restrict__ bsum) {
    ScanJob J = js.j[blockIdx.y];
    int b = blockIdx.x, t = threadIdx.x;
    int C = (J.N + SCAN_G - 1) / SCAN_G;
    int tseg = (C + 255) / 256;
    int base = b * C + t * tseg;
    int endv = min(base + tseg, min((b + 1) * C, J.N));
    int tsum = 0;
    for (int i = base; i < endv; i++) tsum += J.cnt[i];
    __shared__ int s[256];
    s[t] = tsum; __syncthreads();
    for (int o = 1; o < 256; o <<= 1) {
        int v = (t >= o) ? s[t - o] : 0;
        __syncthreads(); s[t] += v; __syncthreads();
    }
    if (t == 255) bsum[blockIdx.y * SCAN_G + b] = s[255];
}

__global__ void scan2_kernel(int* __restrict__ bsum) {
    int j = blockIdx.x, t = threadIdx.x;  // 64 threads
    __shared__ int s[SCAN_G];
    int v = bsum[j * SCAN_G + t];
    s[t] = v; __syncthreads();
    for (int o = 1; o < SCAN_G; o <<= 1) {
        int x = (t >= o) ? s[t - o] : 0;
        __syncthreads(); s[t] += x; __syncthreads();
    }
    bsum[j * SCAN_G + t] = s[t] - v;  // exclusive
}

__global__ void scan3_kernel(ScanJobs js, const int* __restrict__ bsum) {
    ScanJob J = js.j[blockIdx.y];
    int b = blockIdx.x, t = threadIdx.x;
    int C = (J.N + SCAN_G - 1) / SCAN_G;
    int tseg = (C + 255) / 256;
    int base = b * C + t * tseg;
    int endv = min(base + tseg, min((b + 1) * C, J.N));
    int tsum = 0;
    for (int i = base; i < endv; i++) tsum += J.cnt[i];
    __shared__ int s[256];
    s[t] = tsum; __syncthreads();
    for (int o = 1; o < 256; o <<= 1) {
        int v = (t >= o) ? s[t - o] : 0;
        __syncthreads(); s[t] += v; __syncthreads();
    }
    int running = bsum[blockIdx.y * SCAN_G + b] + (s[t] - tsum);
    for (int i = base; i < endv; i++) {
        J.off[i] = running;
        J.cur[i] = running;
        running += J.cnt[i];
    }
    if (base < J.N && endv == J.N) J.off[J.N] = running;
}

struct BJob { const int* dst; const int* val; int n; int* cur; int* csr; };
__global__ void bin5_kernel(BJob a, BJob b, BJob c, BJob d, BJob e) {
    BJob js[5] = {a, b, c, d, e};
    BJob J = js[blockIdx.y];
    int i = blockIdx.x * 256 + threadIdx.x;
    if (i < J.n) {
        int p = atomicAdd(&J.cur[J.dst[i]], 1);
        J.csr[p] = J.val[i];
    }
}

// ---------------------------------------------------------------------------
// CSR gather kernels (replace the atomic scatters). One launch covers both
// post (w < Np) and user (w - Np < Nu) destinations.
// ---------------------------------------------------------------------------
__global__ void gather_all_kernel(const float* __restrict__ hu) {
    int w = (blockIdx.x * 256 + threadIdx.x) >> 5;
    int lane = threadIdx.x & 31;
    if (w < Np) {
        float4 p = gath(gS.csr_pub_v, gS.off_pub_v[w], gS.off_pub_v[w + 1], hu, lane);
        float4 c = gath(gS.csr_com_v, gS.off_com_v[w], gS.off_com_v[w + 1], hu, lane);
        ((float4*)gS.agg_pub)[(size_t)w * 32 + lane] = p;
        ((float4*)gS.agg_com)[(size_t)w * 32 + lane] = c;
    } else {
        int u = w - Np;
        if (u >= Nu) return;
        float4 a = gath(gS.csr_ucu_v, gS.off_ucu_v[u], gS.off_ucu_v[u + 1], hu, lane);
        ((float4*)gS.agg_ucu)[(size_t)u * 32 + lane] = a;
    }
}

// ctx gather (comment/publish post means) + conv ctx + blend into h_user
__global__ void ctx_blend_kernel() {
    int u = (blockIdx.x * 256 + threadIdx.x) >> 5;
    int lane = threadIdx.x & 31;
    if (u >= Nu) return;
    float4 g1 = gath(gS.csr_com_u, gS.off_com_u[u], gS.off_com_u[u + 1], gS.post_enc, lane);
    float4 g2 = gath(gS.csr_pub_u, gS.off_pub_u[u], gS.off_pub_u[u + 1], gS.post_enc, lane);
    float s1 = 0.3f * gS.inv_com_u[u];
    float s2 = 0.5f * gS.inv_pub_u[u];
    float4 cv = ((const float4*)gS.ctx)[(size_t)u * 32 + lane];
    cv.x += s1 * g1.x + s2 * g2.x;
    cv.y += s1 * g1.y + s2 * g2.y;
    cv.z += s1 * g1.z + s2 * g2.z;
    cv.w += s1 * g1.w + s2 * g2.w;
    float4 h = ((const float4*)gS.h_user)[(size_t)u * 32 + lane];
    h.x = 0.7f * h.x + 0.3f * cv.x;
    h.y = 0.7f * h.y + 0.3f * cv.y;
    h.z = 0.7f * h.z + 0.3f * cv.z;
    h.w = 0.7f * h.w + 0.3f * cv.w;
    ((float4*)gS.h_user)[(size_t)u * 32 + lane] = h;
}

// ---------------------------------------------------------------------------
// Misc small kernels
// ---------------------------------------------------------------------------
__global__ void avgpost_kernel(const float* __restrict__ post_x) {
    int col = threadIdx.x;                 // 256 threads = 256 cols
    float s = 0.f;
    for (int r = blockIdx.x; r < Np; r += gridDim.x)
        s += post_x[(size_t)r * IN + col];
    atomicAdd(&gS.avgpost[col], s);
}

__global__ void cvec_kernel(const float* __restrict__ conv_W, const float* __restrict__ conv_b) {
    int c = threadIdx.x;                   // 128 threads
    float s = conv_b[c];
    const float scale = 1.f / (float)Np;
    for (int k = 0; k < IN; k++)
        s += gS.avgpost[k] * scale * conv_W[(size_t)(EF + k) * H + c];
    gS.cvec[c] = s;
}

// Column sums over rows with deg>0
__global__ void colsum_kernel(const float* __restrict__ buf, const int* __restrict__ deg,
                              int Nr, float* __restrict__ gm) {
    __shared__ float s[128];
    if (threadIdx.x < 128) s[threadIdx.x] = 0.f;
    __syncthreads();
    int col = threadIdx.x & 127, sub = threadIdx.x >> 7;
    float local = 0.f;
    for (int r = blockIdx.x * 2 + sub; r < Nr; r += gridDim.x * 2)
        if (deg[r] > 0) local += buf[(size_t)r * 128 + col];
    atomicAdd(&s[col], local);
    __syncthreads();
    if (threadIdx.x < 128) atomicAdd(&gm[threadIdx.x], s[threadIdx.x]);
}

// fix_zero_degree + LayerNorm (+ optional leaky relu). One warp per row.
template <bool LRELU>
__global__ void fix_ln_kernel(const float* __restrict__ hn, const float* __restrict__ init,
                              const int* __restrict__ deg, const float* __restrict__ gm,
                              const int* __restrict__ nzp,
                              const float* __restrict__ g, const float* __restrict__ b,
                              int Nr, float* __restrict__ out) {
    int w = (blockIdx.x * blockDim.x + threadIdx.x) >> 5;
    int lane = threadIdx.x & 31;
    if (w >= Nr) return;
    float4 v;
    if (deg[w] == 0) {
        float nz = fmaxf((float)(*nzp), 1.f);
        float4 e = ((const float4*)init)[(size_t)w * 32 + lane];
        float4 gv = ((const float4*)gm)[lane];
        v.x = 0.9f * e.x + 0.1f * gv.x / nz;
        v.y = 0.9f * e.y + 0.1f * gv.y / nz;
        v.z = 0.9f * e.z + 0.1f * gv.z / nz;
        v.w = 0.9f * e.w + 0.1f * gv.w / nz;
    } else {
        v = ((const float4*)hn)[(size_t)w * 32 + lane];
    }
    float s  = warp_sum(v.x + v.y + v.z + v.w);
    float ss = warp_sum(v.x * v.x + v.y * v.y + v.z * v.z + v.w * v.w);
    float mean = s * (1.f / 128.f);
    float var = ss * (1.f / 128.f) - mean * mean;
    float r = rsqrtf(var + 1e-5f);
    float4 gg = ((const float4*)g)[lane], bb = ((const float4*)b)[lane];
    v.x = (v.x - mean) * r * gg.x + bb.x;
    v.y = (v.y - mean) * r * gg.y + bb.y;
    v.z = (v.z - mean) * r * gg.z + bb.z;
    v.w = (v.w - mean) * r * gg.w + bb.w;
    if (LRELU) { v.x = lrelu(v.x); v.y = lrelu(v.y); v.z = lrelu(v.z); v.w = lrelu(v.w); }
    ((float4*)out)[(size_t)w * 32 + lane] = v;
}

// Final tiny GEMM: out[Nu,4] = T[Nu,128] @ W2[128,4] + b2. One warp per row.
__global__ void cls2_kernel(const float* __restrict__ T, const float* __restrict__ W2,
                            const float* __restrict__ b2, float* __restrict__ out, int Nr) {
    int w = (blockIdx.x * blockDim.x + threadIdx.x) >> 5;
    int lane = threadIdx.x & 31;
    if (w >= Nr) return;
    float4 t = ((const float4*)T)[(size_t)w * 32 + lane];
    float tv[4] = {t.x, t.y, t.z, t.w};
    float a0 = 0.f, a1 = 0.f, a2 = 0.f, a3 = 0.f;
    const float4* W4 = (const float4*)W2;  // row k of [128][4] = one float4
#pragma unroll
    for (int j = 0; j < 4; j++) {
        float4 wr = W4[lane * 4 + j];
        a0 += tv[j] * wr.x; a1 += tv[j] * wr.y; a2 += tv[j] * wr.z; a3 += tv[j] * wr.w;
    }
    a0 = warp_sum(a0); a1 = warp_sum(a1); a2 = warp_sum(a2); a3 = warp_sum(a3);
    if (lane == 0) {
        out[(size_t)w * 4 + 0] = a0 + b2[0];
        out[(size_t)w * 4 + 1] = a1 + b2[1];
        out[(size_t)w * 4 + 2] = a2 + b2[2];
        out[(size_t)w * 4 + 3] = a3 + b2[3];
    }
}

// ---------------------------------------------------------------------------
// Host orchestration
// ---------------------------------------------------------------------------
extern "C" void kernel_launch(void* const* d_in, const int* in_sizes, int n_in,
                              void* d_out, int out_size) {
    const float* user_x      = (const float*)d_in[0];
    const float* post_x      = (const float*)d_in[1];
    const float* parent_feat = (const float*)d_in[2];
    const float* user_proj_W = (const float*)d_in[3];
    const float* user_proj_b = (const float*)d_in[4];
    const float* post_proj_W = (const float*)d_in[5];
    const float* post_proj_b = (const float*)d_in[6];
    const float* conv_W      = (const float*)d_in[7];
    const float* conv_b      = (const float*)d_in[8];
    const float* conv_g      = (const float*)d_in[9];
    const float* conv_beta   = (const float*)d_in[10];
    const float* uce_W       = (const float*)d_in[11];
    const float* uce_b       = (const float*)d_in[12];
    const float* Wself       = (const float*)d_in[13];
    const float* bself       = (const float*)d_in[14];
    const float* Wneigh      = (const float*)d_in[15];
    const float* bneigh      = (const float*)d_in[16];
    const float* ln_user_g   = (const float*)d_in[17];
    const float* ln_user_b   = (const float*)d_in[18];
    const float* ln_post_g   = (const float*)d_in[19];
    const float* ln_post_b   = (const float*)d_in[20];
    const float* cls_W1      = (const float*)d_in[21];
    const float* cls_b1      = (const float*)d_in[22];
    const float* cls_W2      = (const float*)d_in[23];
    const float* cls_b2      = (const float*)d_in[24];
    const int* publish_u     = (const int*)d_in[25];
    const int* publish_v     = (const int*)d_in[26];
    const int* comment_u     = (const int*)d_in[27];
    const int* comment_v     = (const int*)d_in[28];
    const int* ucu_u         = (const int*)d_in[29];
    const int* ucu_v         = (const int*)d_in[30];
    float* out = (float*)d_out;

    Scratch* S = nullptr;
    cudaGetSymbolAddress((void**)&S, gS);

    // --- zero per-launch accumulators ---------------------------------------
    cudaMemsetAsync(S->cnt_pub_u, 0, sizeof(int) * (size_t)(4 * Nu + 2 * Np), 0);
    cudaMemsetAsync(S->nz, 0, sizeof(int) * 4, 0);
    cudaMemsetAsync(S->avgpost, 0, sizeof(float) * IN, 0);
    cudaMemsetAsync(S->ctx, 0, sizeof(float) * (size_t)Nu * H, 0);

    // --- counts / degrees ----------------------------------------------------
    {
        CJob c0 = {publish_u, Ep, S->cnt_pub_u};
        CJob c1 = {publish_v, Ep, S->cnt_pub_v};
        CJob c2 = {comment_u, Ec, S->cnt_com_u};
        CJob c3 = {comment_v, Ec, S->cnt_com_v};
        CJob c4 = {ucu_u, Eu, S->cnt_ucu_u};
        CJob c5 = {ucu_v, Eu, S->cnt_ucu_v};
        dim3 g((Ec + 255) / 256, 6);
        count6_kernel<<<g, 256>>>(c0, c1, c2, c3, c4, c5);
    }
    prep_user_kernel<<<(Nu + 255) / 256, 256>>>();
    prep_post_kernel<<<(Np + 255) / 256, 256>>>();

    // --- CSR build (scan + bin) ----------------------------------------------
    {
        ScanJobs sj;
        sj.j[0] = {S->cnt_pub_v, Np, S->off_pub_v, S->cur_pub_v};
        sj.j[1] = {S->cnt_com_v, Np, S->off_com_v, S->cur_com_v};
        sj.j[2] = {S->cnt_ucu_v, Nu, S->off_ucu_v, S->cur_ucu_v};
        sj.j[3] = {S->cnt_com_u, Nu, S->off_com_u, S->cur_com_u};
        sj.j[4] = {S->cnt_pub_u, Nu, S->off_pub_u, S->cur_pub_u};
        dim3 g1(SCAN_G, 5);
        scan1_kernel<<<g1, 256>>>(sj, S->blocksums);
        scan2_kernel<<<5, SCAN_G>>>(S->blocksums);
        scan3_kernel<<<g1, 256>>>(sj, S->blocksums);

        BJob b0 = {publish_v, publish_u, Ep, S->cur_pub_v, S->csr_pub_v};
        BJob b1 = {comment_v, comment_u, Ec, S->cur_com_v, S->csr_com_v};
        BJob b2 = {ucu_v, ucu_u, Eu, S->cur_ucu_v, S->csr_ucu_v};
        BJob b3 = {comment_u, comment_v, Ec, S->cur_com_u, S->csr_com_u};
        BJob b4 = {publish_u, publish_v, Ep, S->cur_pub_u, S->csr_pub_u};
        dim3 gb((Ec + 255) / 256, 5);
        bin5_kernel<<<gb, 256>>>(b0, b1, b2, b3, b4);
    }

    // --- constants -----------------------------------------------------------
    avgpost_kernel<<<512, 256>>>(post_x);
    cvec_kernel<<<1, 128>>>(conv_W, conv_b);

    // --- weight preprocessing (transpose + tf32) -----------------------------
    {
        WJobs js;
        js.j[0] = {user_proj_W, nullptr, S->Wt_up, 256};
        js.j[1] = {post_proj_W, nullptr, S->Wt_pp, 256};
        js.j[2] = {uce_W, nullptr, S->Wt_uce, 256};
        js.j[3] = {cls_W1, nullptr, S->Wt_cls, 128};
        js.j[4] = {conv_W, nullptr, S->Wt_conv, 64};   // conv_W[:64] rows only
        for (int l = 0; l < 2; l++) {
            js.j[5 + 5 * l + 0] = {Wself + (size_t)(l * 3 + 0) * HH, Wself + (size_t)(l * 3 + 1) * HH, S->Wt_ss[l], 128};
            js.j[5 + 5 * l + 1] = {Wneigh + (size_t)(l * 3 + 0) * HH, nullptr, S->Wt_n0[l], 128};
            js.j[5 + 5 * l + 2] = {Wneigh + (size_t)(l * 3 + 1) * HH, nullptr, S->Wt_n1[l], 128};
            js.j[5 + 5 * l + 3] = {Wself + (size_t)(l * 3 + 2) * HH, nullptr, S->Wt_s2[l], 128};
            js.j[5 + 5 * l + 4] = {Wneigh + (size_t)(l * 3 + 2) * HH, nullptr, S->Wt_n2[l], 128};
        }
        dim3 g(128, 15);
        wprep_kernel<<<g, 256>>>(js);
    }
    bcomb_kernel<<<1, 128>>>(bself, bneigh);

    Seg z = {nullptr, nullptr, nullptr, 0};

    // --- input projections (tf32); init copies fused into epilogue -----------
    {
        Seg s = {user_x, S->Wt_up, nullptr, 256};
        gemm_tf32<1><<<(Nu + 127) / 128, 256>>>(s, z, z, 1, user_proj_b, S->h_user, S->init_user, Nu);
    }
    {
        Seg s = {post_x, S->Wt_pp, nullptr, 256};
        gemm_tf32<1><<<(Np + 127) / 128, 256>>>(s, z, z, 1, post_proj_b, S->h_post, S->init_post, Np);
    }
    {
        Seg s = {post_x, S->Wt_uce, nullptr, 256};
        gemm_tf32<2><<<(Np + 127) / 128, 256>>>(s, z, z, 1, uce_b, S->post_enc, nullptr, Np);
    }

    // --- ctx: tensor-core conv edge-GEMM scatter + CSR gathers + blend --------
    conv_mma_kernel<<<(Eu + 127) / 128, 256>>>(parent_feat, S->Wt_conv, S->cvec, conv_g, conv_beta, ucu_u, S->ctx, Eu);
    ctx_blend_kernel<<<((size_t)Nu * 32 + 255) / 256, 256>>>();

    // --- SAGE layers ----------------------------------------------------------
    for (int l = 0; l < 2; l++) {
        gather_all_kernel<<<((size_t)(Np + Nu) * 32 + 255) / 256, 256>>>(S->h_user);

        // post_new = h_post@(Ws0+Ws1) + mean_pub@Wn0 + mean_com@Wn1 + b_post[l]
        {
            Seg sA = {S->h_post, S->Wt_ss[l], nullptr, 128};
            Seg sB = {S->agg_pub, S->Wt_n0[l], S->inv_pub_v, 128};
            Seg sC = {S->agg_com, S->Wt_n1[l], S->inv_com_v, 128};
            gemm_tf32<0><<<(Np + 127) / 128, 256>>>(sA, sB, sC, 3, S->b_post[l], S->post_new, nullptr, Np);
        }
        // user_new = h_user@Ws2 + mean_ucu@Wn2 + b_user[l]
        {
            Seg sA = {S->h_user, S->Wt_s2[l], nullptr, 128};
            Seg sB = {S->agg_ucu, S->Wt_n2[l], S->inv_ucu_v, 128};
            gemm_tf32<0><<<(Nu + 127) / 128, 256>>>(sA, sB, z, 2, S->b_user[l], S->user_new, nullptr, Nu);
        }

        cudaMemsetAsync(S->gm_user, 0, sizeof(float) * 2 * H, 0);  // gm_user + gm_post
        colsum_kernel<<<512, 256>>>(S->user_new, S->deg_user, Nu, S->gm_user);
        colsum_kernel<<<512, 256>>>(S->post_new, S->deg_post, Np, S->gm_post);
        if (l == 0) {
            fix_ln_kernel<true><<<((size_t)Nu * 32 + 255) / 256, 256>>>(S->user_new, S->init_user, S->deg_user, S->gm_user, &S->nz[0], ln_user_g, ln_user_b, Nu, S->h_user);
            fix_ln_kernel<true><<<((size_t)Np * 32 + 255) / 256, 256>>>(S->post_new, S->init_post, S->deg_post, S->gm_post, &S->nz[1], ln_post_g, ln_post_b, Np, S->h_post);
        } else {
            fix_ln_kernel<false><<<((size_t)Nu * 32 + 255) / 256, 256>>>(S->user_new, S->init_user, S->deg_user, S->gm_user, &S->nz[0], ln_user_g, ln_user_b, Nu, S->h_user);
            fix_ln_kernel<false><<<((size_t)Np * 32 + 255) / 256, 256>>>(S->post_new, S->init_post, S->deg_post, S->gm_post, &S->nz[1], ln_post_g, ln_post_b, Np, S->h_post);
        }
    }

    // --- classifier -----------------------------------------------------------
    {
        Seg s = {S->h_user, S->Wt_cls, nullptr, 128};
        gemm_tf32<1><<<(Nu + 127) / 128, 256>>>(s, z, z, 1, cls_b1, S->user_new, nullptr, Nu);
    }
    cls2_kernel<<<((size_t)Nu * 32 + 255) / 256, 256>>>(S->user_new, cls_W2, cls_b2, out, Nu);
}

// round 11
// speedup vs baseline: 1.6391x; 1.1168x over previous
#include <cuda_runtime.h>

// ---------------------------------------------------------------------------
// Problem constants
// ---------------------------------------------------------------------------
constexpr int Nu = 50000, Np = 20000, IN = 256, EF = 64, H = 128;
constexpr int Ep = 200000, Ec = 800000, Eu = 300000;
constexpr int HH = H * H;
constexpr int SCAN_G = 64;

// ---------------------------------------------------------------------------
// Scratch (device global; allocation-free contract)
// ---------------------------------------------------------------------------
struct alignas(16) Scratch {
    float h_user[(size_t)Nu * H];
    float init_user[(size_t)Nu * H];
    float ctx[(size_t)Nu * H];
    float user_new[(size_t)Nu * H];   // also reused as classifier tmp
    float agg_ucu[(size_t)Nu * H];
    float h_post[(size_t)Np * H];
    float init_post[(size_t)Np * H];
    float post_enc[(size_t)Np * H];
    float post_new[(size_t)Np * H];
    float agg_pub[(size_t)Np * H];
    float agg_com[(size_t)Np * H];
    int cnt_pub_u[Nu]; int cnt_com_u[Nu]; int cnt_ucu_u[Nu]; int cnt_ucu_v[Nu];
    int cnt_pub_v[Np]; int cnt_com_v[Np];
    float inv_pub_u[Nu]; float inv_com_u[Nu]; float inv_ucu_v[Nu];
    float inv_pub_v[Np]; float inv_com_v[Np];
    int deg_user[Nu]; int deg_post[Np];
    float avgpost[IN];
    float cvec[H];
    float gm_user[H]; float gm_post[H];   // contiguous: single memset
    int nz[4];                            // padded so next member is 16B-aligned
    // CSR structures (built once per launch)
    int off_pub_v[Np + 1]; int off_com_v[Np + 1]; int off_ucu_v[Nu + 1];
    int off_com_u[Nu + 1]; int off_pub_u[Nu + 1];
    int cur_pub_v[Np]; int cur_com_v[Np]; int cur_ucu_v[Nu];
    int cur_com_u[Nu]; int cur_pub_u[Nu];
    int blocksums[5 * SCAN_G];
    int csr_pub_v[Ep]; int csr_com_v[Ec]; int csr_ucu_v[Eu];
    int csr_com_u[Ec]; int csr_pub_u[Ep];
    // tf32-converted, n-major (Wt[n][k]) weights. 16B alignment REQUIRED for
    // the uint4 loads in the mma kernels (R3 misaligned-address crash).
    alignas(16) unsigned Wt_up[128 * 256];
    alignas(16) unsigned Wt_pp[128 * 256];
    alignas(16) unsigned Wt_uce[128 * 256];
    alignas(16) unsigned Wt_cls[128 * 128];
    alignas(16) unsigned Wt_conv[128 * 64];
    alignas(16) unsigned Wt_ss[2][HH];   // Wself(l,0)+Wself(l,1)
    alignas(16) unsigned Wt_n0[2][HH];
    alignas(16) unsigned Wt_n1[2][HH];
    alignas(16) unsigned Wt_s2[2][HH];
    alignas(16) unsigned Wt_n2[2][HH];
    float b_post[2][H]; float b_user[2][H];
};
__device__ Scratch gS;

// ---------------------------------------------------------------------------
// Helpers
// ---------------------------------------------------------------------------
__device__ __forceinline__ float warp_sum(float v) {
#pragma unroll
    for (int o = 16; o; o >>= 1) v += __shfl_xor_sync(0xffffffffu, v, o);
    return v;
}

__device__ __forceinline__ void red2(float* p, float a, float b) {
    asm volatile("red.global.add.v2.f32 [%0], {%1,%2};"
                 :: "l"(p), "f"(a), "f"(b) : "memory");
}

__device__ __forceinline__ float lrelu(float x) { return x >= 0.f ? x : 0.01f * x; }

__device__ __forceinline__ unsigned f2tf(float x) {
    unsigned r;
    asm("cvt.rna.tf32.f32 %0, %1;" : "=r"(r) : "f"(x));
    return r;
}

__device__ __forceinline__ void mma_tf32(float c[4], const unsigned a[4], const unsigned b[2]) {
    asm volatile(
        "mma.sync.aligned.m16n8k8.row.col.f32.tf32.tf32.f32 "
        "{%0,%1,%2,%3},{%4,%5,%6,%7},{%8,%9},{%0,%1,%2,%3};"
        : "+f"(c[0]), "+f"(c[1]), "+f"(c[2]), "+f"(c[3])
        : "r"(a[0]), "r"(a[1]), "r"(a[2]), "r"(a[3]), "r"(b[0]), "r"(b[1]));
}

// Gather-sum a 512B feature row range via CSR (dual accumulator for MLP=2).
__device__ __forceinline__ float4 gath(const int* __restrict__ csr, int beg, int end,
                                       const float* __restrict__ feat, int lane) {
    float4 a = make_float4(0.f, 0.f, 0.f, 0.f);
    float4 b = make_float4(0.f, 0.f, 0.f, 0.f);
    int i = beg;
    for (; i + 1 < end; i += 2) {
        int s0 = csr[i], s1 = csr[i + 1];
        float4 v0 = ((const float4*)feat)[(size_t)s0 * 32 + lane];
        float4 v1 = ((const float4*)feat)[(size_t)s1 * 32 + lane];
        a.x += v0.x; a.y += v0.y; a.z += v0.z; a.w += v0.w;
        b.x += v1.x; b.y += v1.y; b.z += v1.z; b.w += v1.w;
    }
    if (i < end) {
        int s0 = csr[i];
        float4 v0 = ((const float4*)feat)[(size_t)s0 * 32 + lane];
        a.x += v0.x; a.y += v0.y; a.z += v0.z; a.w += v0.w;
    }
    a.x += b.x; a.y += b.y; a.z += b.z; a.w += b.w;
    return a;
}

// ---------------------------------------------------------------------------
// tf32 tensor-core GEMM, up to 3 independent JOBS per launch (block ranges),
// each job with up to 3 fused K-segments:
//   C[M,128] = act( sum_s (rs_s ⊙ A_s[M,Ks]) @ W_s[Ks,128] + bias )
// W pre-transposed+tf32 (Wt[n][k], n-major). BM=128,BN=128,BK=16; 8 warps,
// each computes 32x64 via m16n8k8. act: 0=none, 1=lrelu, 2=relu (runtime).
// If C2 != nullptr, activated result also written to C2 (fused copy).
// ---------------------------------------------------------------------------
struct Seg { const float* A; const unsigned* Wt; const float* rs; int K; };
struct GemmJob {
    Seg s0, s1, s2; int nseg;
    const float* bias; float* C; float* C2; int M; int act;
};

__global__ __launch_bounds__(256, 2) void gemm_multi(
    GemmJob j0, GemmJob j1, GemmJob j2, int start1, int start2)
{
    __shared__ __align__(16) unsigned As[128][20];
    __shared__ __align__(16) unsigned Bs[128][20];
    const int tid = threadIdx.x;
    const int lane = tid & 31, warp = tid >> 5;
    const int gid = lane >> 2, q = lane & 3;
    const int wm = warp & 3, wn = warp >> 2;

    GemmJob J;
    int lb = blockIdx.x;
    if (lb >= start2)      { J = j2; lb -= start2; }
    else if (lb >= start1) { J = j1; lb -= start1; }
    else                   { J = j0; }
    const int M = J.M;
    const int rowBase = lb * 128;
    const int lrow = tid >> 2;            // 0..63
    const int lk4 = (tid & 3) * 4;        // 0,4,8,12

    float acc[2][8][4];
#pragma unroll
    for (int mt = 0; mt < 2; mt++)
#pragma unroll
        for (int nt = 0; nt < 8; nt++)
#pragma unroll
            for (int i = 0; i < 4; i++) acc[mt][nt][i] = 0.f;

    Seg segs[3] = {J.s0, J.s1, J.s2};
    for (int s = 0; s < J.nseg; s++) {
        const float* A = segs[s].A;
        const unsigned* Wt = segs[s].Wt;
        const float* rs = segs[s].rs;
        const int K = segs[s].K;
        int r0 = rowBase + lrow;      if (r0 > M - 1) r0 = M - 1;
        int r1 = rowBase + lrow + 64; if (r1 > M - 1) r1 = M - 1;
        const float sc0 = rs ? rs[r0] : 1.f;
        const float sc1 = rs ? rs[r1] : 1.f;

        for (int k0 = 0; k0 < K; k0 += 16) {
            float4 av0 = *(const float4*)&A[(size_t)r0 * K + k0 + lk4];
            float4 av1 = *(const float4*)&A[(size_t)r1 * K + k0 + lk4];
            uint4 u0 = make_uint4(f2tf(av0.x * sc0), f2tf(av0.y * sc0),
                                  f2tf(av0.z * sc0), f2tf(av0.w * sc0));
            uint4 u1 = make_uint4(f2tf(av1.x * sc1), f2tf(av1.y * sc1),
                                  f2tf(av1.z * sc1), f2tf(av1.w * sc1));
            *(uint4*)&As[lrow][lk4] = u0;
            *(uint4*)&As[lrow + 64][lk4] = u1;
            *(uint4*)&Bs[lrow][lk4]      = *(const uint4*)&Wt[(size_t)lrow * K + k0 + lk4];
            *(uint4*)&Bs[lrow + 64][lk4] = *(const uint4*)&Wt[(size_t)(lrow + 64) * K + k0 + lk4];
            __syncthreads();

#pragma unroll
            for (int kk = 0; kk < 16; kk += 8) {
                unsigned a[2][4], b[8][2];
#pragma unroll
                for (int mt = 0; mt < 2; mt++) {
                    int r = wm * 32 + mt * 16 + gid;
                    a[mt][0] = As[r][kk + q];
                    a[mt][1] = As[r + 8][kk + q];
                    a[mt][2] = As[r][kk + q + 4];
                    a[mt][3] = As[r + 8][kk + q + 4];
                }
#pragma unroll
                for (int nt = 0; nt < 8; nt++) {
                    int n = wn * 64 + nt * 8 + gid;
                    b[nt][0] = Bs[n][kk + q];
                    b[nt][1] = Bs[n][kk + q + 4];
                }
#pragma unroll
                for (int mt = 0; mt < 2; mt++)
#pragma unroll
                    for (int nt = 0; nt < 8; nt++)
                        mma_tf32(acc[mt][nt], a[mt], b[nt]);
            }
            __syncthreads();
        }
    }

    // Epilogue: bias + activation + store
    const int act = J.act;
#pragma unroll
    for (int mt = 0; mt < 2; mt++) {
        int row0 = rowBase + wm * 32 + mt * 16 + gid;
        int row1 = row0 + 8;
#pragma unroll
        for (int nt = 0; nt < 8; nt++) {
            int col = wn * 64 + nt * 8 + q * 2;
            float b0 = J.bias[col], b1 = J.bias[col + 1];
            float v0 = acc[mt][nt][0] + b0, v1 = acc[mt][nt][1] + b1;
            float v2 = acc[mt][nt][2] + b0, v3 = acc[mt][nt][3] + b1;
            if (act == 1) { v0 = lrelu(v0); v1 = lrelu(v1); v2 = lrelu(v2); v3 = lrelu(v3); }
            else if (act == 2) {
                v0 = fmaxf(v0, 0.f); v1 = fmaxf(v1, 0.f);
                v2 = fmaxf(v2, 0.f); v3 = fmaxf(v3, 0.f);
            }
            if (row0 < M) {
                *(float2*)&J.C[(size_t)row0 * 128 + col] = make_float2(v0, v1);
                if (J.C2) *(float2*)&J.C2[(size_t)row0 * 128 + col] = make_float2(v0, v1);
            }
            if (row1 < M) {
                *(float2*)&J.C[(size_t)row1 * 128 + col] = make_float2(v2, v3);
                if (J.C2) *(float2*)&J.C2[(size_t)row1 * 128 + col] = make_float2(v2, v3);
            }
        }
    }
}

// ---------------------------------------------------------------------------
// conv via tensor cores: per-edge cc = relu(LN(parent_feat@convW + cvec)),
// then ctx[ucu_u[e]] += cc. BM=128 edges, N=128, K=64.
// ---------------------------------------------------------------------------
__global__ __launch_bounds__(256, 2) void conv_mma_kernel(
    const float* __restrict__ A, const unsigned* __restrict__ Wt,
    const float* __restrict__ cvec, const float* __restrict__ gw,
    const float* __restrict__ be, const int* __restrict__ uidx,
    float* __restrict__ ctx, int M)
{
    __shared__ __align__(16) unsigned As[128][20];
    __shared__ __align__(16) unsigned Bs[128][20];
    __shared__ float rsum[128], rssq[128];
    const int tid = threadIdx.x;
    const int lane = tid & 31, warp = tid >> 5;
    const int gid = lane >> 2, q = lane & 3;
    const int wm = warp & 3, wn = warp >> 2;
    const int rowBase = blockIdx.x * 128;
    const int lrow = tid >> 2;
    const int lk4 = (tid & 3) * 4;

    float acc[2][8][4];
#pragma unroll
    for (int mt = 0; mt < 2; mt++)
#pragma unroll
        for (int nt = 0; nt < 8; nt++)
#pragma unroll
            for (int i = 0; i < 4; i++) acc[mt][nt][i] = 0.f;

    int r0 = rowBase + lrow;      if (r0 > M - 1) r0 = M - 1;
    int r1 = rowBase + lrow + 64; if (r1 > M - 1) r1 = M - 1;

    if (tid < 128) { rsum[tid] = 0.f; rssq[tid] = 0.f; }

    for (int k0 = 0; k0 < 64; k0 += 16) {
        float4 av0 = *(const float4*)&A[(size_t)r0 * 64 + k0 + lk4];
        float4 av1 = *(const float4*)&A[(size_t)r1 * 64 + k0 + lk4];
        *(uint4*)&As[lrow][lk4] = make_uint4(f2tf(av0.x), f2tf(av0.y), f2tf(av0.z), f2tf(av0.w));
        *(uint4*)&As[lrow + 64][lk4] = make_uint4(f2tf(av1.x), f2tf(av1.y), f2tf(av1.z), f2tf(av1.w));
        *(uint4*)&Bs[lrow][lk4]      = *(const uint4*)&Wt[(size_t)lrow * 64 + k0 + lk4];
        *(uint4*)&Bs[lrow + 64][lk4] = *(const uint4*)&Wt[(size_t)(lrow + 64) * 64 + k0 + lk4];
        __syncthreads();
#pragma unroll
        for (int kk = 0; kk < 16; kk += 8) {
            unsigned a[2][4], b[8][2];
#pragma unroll
            for (int mt = 0; mt < 2; mt++) {
                int r = wm * 32 + mt * 16 + gid;
                a[mt][0] = As[r][kk + q];
                a[mt][1] = As[r + 8][kk + q];
                a[mt][2] = As[r][kk + q + 4];
                a[mt][3] = As[r + 8][kk + q + 4];
            }
#pragma unroll
            for (int nt = 0; nt < 8; nt++) {
                int n = wn * 64 + nt * 8 + gid;
                b[nt][0] = Bs[n][kk + q];
                b[nt][1] = Bs[n][kk + q + 4];
            }
#pragma unroll
            for (int mt = 0; mt < 2; mt++)
#pragma unroll
                for (int nt = 0; nt < 8; nt++)
                    mma_tf32(acc[mt][nt], a[mt], b[nt]);
        }
        __syncthreads();
    }

    // add cvec; per-row partial sums (row0 uses c0,c1; row1=row0+8 uses c2,c3)
#pragma unroll
    for (int mt = 0; mt < 2; mt++) {
        float ps0 = 0.f, pq0 = 0.f, ps1 = 0.f, pq1 = 0.f;
#pragma unroll
        for (int nt = 0; nt < 8; nt++) {
            int col = wn * 64 + nt * 8 + q * 2;
            float cv0 = cvec[col], cv1 = cvec[col + 1];
            acc[mt][nt][0] += cv0; acc[mt][nt][1] += cv1;
            acc[mt][nt][2] += cv0; acc[mt][nt][3] += cv1;
            ps0 += acc[mt][nt][0] + acc[mt][nt][1];
            pq0 += acc[mt][nt][0] * acc[mt][nt][0] + acc[mt][nt][1] * acc[mt][nt][1];
            ps1 += acc[mt][nt][2] + acc[mt][nt][3];
            pq1 += acc[mt][nt][2] * acc[mt][nt][2] + acc[mt][nt][3] * acc[mt][nt][3];
        }
#pragma unroll
        for (int o = 1; o <= 2; o <<= 1) {
            ps0 += __shfl_xor_sync(0xffffffffu, ps0, o);
            pq0 += __shfl_xor_sync(0xffffffffu, pq0, o);
            ps1 += __shfl_xor_sync(0xffffffffu, ps1, o);
            pq1 += __shfl_xor_sync(0xffffffffu, pq1, o);
        }
        if (q == 0) {
            int rl = wm * 32 + mt * 16 + gid;
            atomicAdd(&rsum[rl], ps0); atomicAdd(&rssq[rl], pq0);
            atomicAdd(&rsum[rl + 8], ps1); atomicAdd(&rssq[rl + 8], pq1);
        }
    }
    __syncthreads();

    // normalize + relu + scatter
#pragma unroll
    for (int mt = 0; mt < 2; mt++) {
        int rl = wm * 32 + mt * 16 + gid;
        int row0 = rowBase + rl, row1 = row0 + 8;
        float m0 = rsum[rl] * (1.f / 128.f);
        float v0 = rssq[rl] * (1.f / 128.f) - m0 * m0;
        float rr0 = rsqrtf(v0 + 1e-5f);
        float m1 = rsum[rl + 8] * (1.f / 128.f);
        float v1 = rssq[rl + 8] * (1.f / 128.f) - m1 * m1;
        float rr1 = rsqrtf(v1 + 1e-5f);
        int u0 = (row0 < M) ? uidx[row0] : -1;
        int u1 = (row1 < M) ? uidx[row1] : -1;
#pragma unroll
        for (int nt = 0; nt < 8; nt++) {
            int col = wn * 64 + nt * 8 + q * 2;
            float g0 = gw[col], g1 = gw[col + 1];
            float b0 = be[col], b1 = be[col + 1];
            if (u0 >= 0) {
                float x0 = fmaxf((acc[mt][nt][0] - m0) * rr0 * g0 + b0, 0.f);
                float x1 = fmaxf((acc[mt][nt][1] - m0) * rr0 * g1 + b1, 0.f);
                red2(&ctx[(size_t)u0 * 128 + col], x0, x1);
            }
            if (u1 >= 0) {
                float x2 = fmaxf((acc[mt][nt][2] - m1) * rr1 * g0 + b0, 0.f);
                float x3 = fmaxf((acc[mt][nt][3] - m1) * rr1 * g1 + b1, 0.f);
                red2(&ctx[(size_t)u1 * 128 + col], x2, x3);
            }
        }
    }
}

// ---------------------------------------------------------------------------
// Weight preprocessing: dst[n*K+k] = tf32(src[k*128+n] (+ src2[k*128+n]))
// ---------------------------------------------------------------------------
struct WJob { const float* src; const float* src2; unsigned* dst; int K; };
struct WJobs { WJob j[15]; };

__global__ void wprep_kernel(WJobs js) {
    WJob J = js.j[blockIdx.y];
    int idx = blockIdx.x * 256 + threadIdx.x;
    if (idx >= 128 * J.K) return;
    int n = idx / J.K, k = idx % J.K;
    float v = J.src[(size_t)k * 128 + n];
    if (J.src2) v += J.src2[(size_t)k * 128 + n];
    J.dst[idx] = f2tf(v);
}

__global__ void bcomb_kernel(const float* __restrict__ bself, const float* __restrict__ bneigh) {
    int c = threadIdx.x;  // 128
#pragma unroll
    for (int l = 0; l < 2; l++) {
        gS.b_post[l][c] = bself[(l * 3 + 0) * H + c] + bself[(l * 3 + 1) * H + c]
                        + bneigh[(l * 3 + 0) * H + c] + bneigh[(l * 3 + 1) * H + c];
        gS.b_user[l][c] = bself[(l * 3 + 2) * H + c] + bneigh[(l * 3 + 2) * H + c];
    }
}

// ---------------------------------------------------------------------------
// Counts / degrees
// ---------------------------------------------------------------------------
struct CJob { const int* idx; int n; int* cnt; };
__global__ void count6_kernel(CJob a, CJob b, CJob c, CJob d, CJob e, CJob f) {
    CJob js[6] = {a, b, c, d, e, f};
    CJob J = js[blockIdx.y];
    int i = blockIdx.x * 256 + threadIdx.x;
    if (i < J.n) atomicAdd(&J.cnt[J.idx[i]], 1);
}

__global__ void prep_user_kernel() {
    int i = blockIdx.x * blockDim.x + threadIdx.x;
    int flag = 0;
    if (i < Nu) {
        int a = gS.cnt_pub_u[i], b = gS.cnt_com_u[i];
        int c = gS.cnt_ucu_u[i], d = gS.cnt_ucu_v[i];
        gS.inv_pub_u[i] = 1.f / (float)(a > 1 ? a : 1);
        gS.inv_com_u[i] = 1.f / (float)(b > 1 ? b : 1);
        gS.inv_ucu_v[i] = 1.f / (float)(d > 1 ? d : 1);
        int deg = a + b + c + d;
        gS.deg_user[i] = deg;
        flag = deg > 0;
    }
    unsigned m = __ballot_sync(0xffffffffu, flag);
    if ((threadIdx.x & 31) == 0) atomicAdd(&gS.nz[0], __popc(m));
}

__global__ void prep_post_kernel() {
    int i = blockIdx.x * blockDim.x + threadIdx.x;
    int flag = 0;
    if (i < Np) {
        int a = gS.cnt_pub_v[i], b = gS.cnt_com_v[i];
        gS.inv_pub_v[i] = 1.f / (float)(a > 1 ? a : 1);
        gS.inv_com_v[i] = 1.f / (float)(b > 1 ? b : 1);
        int deg = a + b;
        gS.deg_post[i] = deg;
        flag = deg > 0;
    }
    unsigned m = __ballot_sync(0xffffffffu, flag);
    if ((threadIdx.x & 31) == 0) atomicAdd(&gS.nz[1], __popc(m));
}

// ---------------------------------------------------------------------------
// CSR build: exclusive scan of counts (3 kernels, 5 jobs batched) + binning
// ---------------------------------------------------------------------------
struct ScanJob { const int* cnt; int N; int* off; int* cur; };
struct ScanJobs { ScanJob j[5]; };

__global__ void scan1_kernel(ScanJobs js, int* __restrict__ bsum) {
    ScanJob J = js.j[blockIdx.y];
    int b = blockIdx.x, t = threadIdx.x;
    int C = (J.N + SCAN_G - 1) / SCAN_G;
    int tseg = (C + 255) / 256;
    int base = b * C + t * tseg;
    int endv = min(base + tseg, min((b + 1) * C, J.N));
    int tsum = 0;
    for (int i = base; i < endv; i++) tsum += J.cnt[i];
    __shared__ int s[256];
    s[t] = tsum; __syncthreads();
    for (int o = 1; o < 256; o <<= 1) {
        int v = (t >= o) ? s[t - o] : 0;
        __syncthreads(); s[t] += v; __syncthreads();
    }
    if (t == 255) bsum[blockIdx.y * SCAN_G + b] = s[255];
}

__global__ void scan2_kernel(int* __restrict__ bsum) {
    int j = blockIdx.x, t = threadIdx.x;  // 64 threads
    __shared__ int s[SCAN_G];
    int v = bsum[j * SCAN_G + t];
    s[t] = v; __syncthreads();
    for (int o = 1; o < SCAN_G; o <<= 1) {
        int x = (t >= o) ? s[t - o] : 0;
        __syncthreads(); s[t] += x; __syncthreads();
    }
    bsum[j * SCAN_G + t] = s[t] - v;  // exclusive
}

__global__ void scan3_kernel(ScanJobs js, const int* __restrict__ bsum) {
    ScanJob J = js.j[blockIdx.y];
    int b = blockIdx.x, t = threadIdx.x;
    int C = (J.N + SCAN_G - 1) / SCAN_G;
    int tseg = (C + 255) / 256;
    int base = b * C + t * tseg;
    int endv = min(base + tseg, min((b + 1) * C, J.N));
    int tsum = 0;
    for (int i = base; i < endv; i++) tsum += J.cnt[i];
    __shared__ int s[256];
    s[t] = tsum; __syncthreads();
    for (int o = 1; o < 256; o <<= 1) {
        int v = (t >= o) ? s[t - o] : 0;
        __syncthreads(); s[t] += v; __syncthreads();
    }
    int running = bsum[blockIdx.y * SCAN_G + b] + (s[t] - tsum);
    for (int i = base; i < endv; i++) {
        J.off[i] = running;
        J.cur[i] = running;
        running += J.cnt[i];
    }
    if (base < J.N && endv == J.N) J.off[J.N] = running;
}

struct BJob { const int* dst; const int* val; int n; int* cur; int* csr; };
__global__ void bin5_kernel(BJob a, BJob b, BJob c, BJob d, BJob e) {
    BJob js[5] = {a, b, c, d, e};
    BJob J = js[blockIdx.y];
    int i = blockIdx.x * 256 + threadIdx.x;
    if (i < J.n) {
        int p = atomicAdd(&J.cur[J.dst[i]], 1);
        J.csr[p] = J.val[i];
    }
}

// ---------------------------------------------------------------------------
// CSR gather kernels (replace the atomic scatters). One launch covers both
// post (w < Np) and user (w - Np < Nu) destinations.
// ---------------------------------------------------------------------------
__global__ void gather_all_kernel(const float* __restrict__ hu) {
    int w = (blockIdx.x * 256 + threadIdx.x) >> 5;
    int lane = threadIdx.x & 31;
    if (w < Np) {
        float4 p = gath(gS.csr_pub_v, gS.off_pub_v[w], gS.off_pub_v[w + 1], hu, lane);
        float4 c = gath(gS.csr_com_v, gS.off_com_v[w], gS.off_com_v[w + 1], hu, lane);
        ((float4*)gS.agg_pub)[(size_t)w * 32 + lane] = p;
        ((float4*)gS.agg_com)[(size_t)w * 32 + lane] = c;
    } else {
        int u = w - Np;
        if (u >= Nu) return;
        float4 a = gath(gS.csr_ucu_v, gS.off_ucu_v[u], gS.off_ucu_v[u + 1], hu, lane);
        ((float4*)gS.agg_ucu)[(size_t)u * 32 + lane] = a;
    }
}

// ctx gather (comment/publish post means) + conv ctx + blend into h_user
__global__ void ctx_blend_kernel() {
    int u = (blockIdx.x * 256 + threadIdx.x) >> 5;
    int lane = threadIdx.x & 31;
    if (u >= Nu) return;
    float4 g1 = gath(gS.csr_com_u, gS.off_com_u[u], gS.off_com_u[u + 1], gS.post_enc, lane);
    float4 g2 = gath(gS.csr_pub_u, gS.off_pub_u[u], gS.off_pub_u[u + 1], gS.post_enc, lane);
    float s1 = 0.3f * gS.inv_com_u[u];
    float s2 = 0.5f * gS.inv_pub_u[u];
    float4 cv = ((const float4*)gS.ctx)[(size_t)u * 32 + lane];
    cv.x += s1 * g1.x + s2 * g2.x;
    cv.y += s1 * g1.y + s2 * g2.y;
    cv.z += s1 * g1.z + s2 * g2.z;
    cv.w += s1 * g1.w + s2 * g2.w;
    float4 h = ((const float4*)gS.h_user)[(size_t)u * 32 + lane];
    h.x = 0.7f * h.x + 0.3f * cv.x;
    h.y = 0.7f * h.y + 0.3f * cv.y;
    h.z = 0.7f * h.z + 0.3f * cv.z;
    h.w = 0.7f * h.w + 0.3f * cv.w;
    ((float4*)gS.h_user)[(size_t)u * 32 + lane] = h;
}

// ---------------------------------------------------------------------------
// Misc small kernels
// ---------------------------------------------------------------------------
__global__ void avgpost_kernel(const float* __restrict__ post_x) {
    int col = threadIdx.x;                 // 256 threads = 256 cols
    float s = 0.f;
    for (int r = blockIdx.x; r < Np; r += gridDim.x)
        s += post_x[(size_t)r * IN + col];
    atomicAdd(&gS.avgpost[col], s);
}

__global__ void cvec_kernel(const float* __restrict__ conv_W, const float* __restrict__ conv_b) {
    int c = threadIdx.x;                   // 128 threads
    float s = conv_b[c];
    const float scale = 1.f / (float)Np;
    for (int k = 0; k < IN; k++)
        s += gS.avgpost[k] * scale * conv_W[(size_t)(EF + k) * H + c];
    gS.cvec[c] = s;
}

// Column sums over rows with deg>0; blockIdx.y: 0=user, 1=post
__global__ void colsum2_kernel() {
    const float* buf = blockIdx.y ? gS.post_new : gS.user_new;
    const int* deg   = blockIdx.y ? gS.deg_post : gS.deg_user;
    float* gm        = blockIdx.y ? gS.gm_post  : gS.gm_user;
    int Nr           = blockIdx.y ? Np : Nu;
    __shared__ float s[128];
    if (threadIdx.x < 128) s[threadIdx.x] = 0.f;
    __syncthreads();
    int col = threadIdx.x & 127, sub = threadIdx.x >> 7;
    float local = 0.f;
    for (int r = blockIdx.x * 2 + sub; r < Nr; r += gridDim.x * 2)
        if (deg[r] > 0) local += buf[(size_t)r * 128 + col];
    atomicAdd(&s[col], local);
    __syncthreads();
    if (threadIdx.x < 128) atomicAdd(&gm[threadIdx.x], s[threadIdx.x]);
}

// fix_zero_degree + LayerNorm (+ optional leaky relu), user+post in ONE
// launch: flat warp index w in [0, Nu+Np).
template <bool LRELU>
__global__ void fixln_all_kernel(const float* __restrict__ lug, const float* __restrict__ lub,
                                 const float* __restrict__ lpg, const float* __restrict__ lpb) {
    int w = (blockIdx.x * blockDim.x + threadIdx.x) >> 5;
    int lane = threadIdx.x & 31;
    const float *hn, *init, *gm, *g, *b;
    const int* deg;
    float* out;
    int nzi;
    if (w < Nu) {
        hn = gS.user_new; init = gS.init_user; deg = gS.deg_user; gm = gS.gm_user;
        g = lug; b = lub; out = gS.h_user; nzi = 0;
    } else {
        w -= Nu;
        if (w >= Np) return;
        hn = gS.post_new; init = gS.init_post; deg = gS.deg_post; gm = gS.gm_post;
        g = lpg; b = lpb; out = gS.h_post; nzi = 1;
    }
    float4 v;
    if (deg[w] == 0) {
        float nz = fmaxf((float)gS.nz[nzi], 1.f);
        float4 e = ((const float4*)init)[(size_t)w * 32 + lane];
        float4 gv = ((const float4*)gm)[lane];
        v.x = 0.9f * e.x + 0.1f * gv.x / nz;
        v.y = 0.9f * e.y + 0.1f * gv.y / nz;
        v.z = 0.9f * e.z + 0.1f * gv.z / nz;
        v.w = 0.9f * e.w + 0.1f * gv.w / nz;
    } else {
        v = ((const float4*)hn)[(size_t)w * 32 + lane];
    }
    float s  = warp_sum(v.x + v.y + v.z + v.w);
    float ss = warp_sum(v.x * v.x + v.y * v.y + v.z * v.z + v.w * v.w);
    float mean = s * (1.f / 128.f);
    float var = ss * (1.f / 128.f) - mean * mean;
    float r = rsqrtf(var + 1e-5f);
    float4 gg = ((const float4*)g)[lane], bb = ((const float4*)b)[lane];
    v.x = (v.x - mean) * r * gg.x + bb.x;
    v.y = (v.y - mean) * r * gg.y + bb.y;
    v.z = (v.z - mean) * r * gg.z + bb.z;
    v.w = (v.w - mean) * r * gg.w + bb.w;
    if (LRELU) { v.x = lrelu(v.x); v.y = lrelu(v.y); v.z = lrelu(v.z); v.w = lrelu(v.w); }
    ((float4*)out)[(size_t)w * 32 + lane] = v;
}

// Final tiny GEMM: out[Nu,4] = T[Nu,128] @ W2[128,4] + b2. One warp per row.
__global__ void cls2_kernel(const float* __restrict__ T, const float* __restrict__ W2,
                            const float* __restrict__ b2, float* __restrict__ out, int Nr) {
    int w = (blockIdx.x * blockDim.x + threadIdx.x) >> 5;
    int lane = threadIdx.x & 31;
    if (w >= Nr) return;
    float4 t = ((const float4*)T)[(size_t)w * 32 + lane];
    float tv[4] = {t.x, t.y, t.z, t.w};
    float a0 = 0.f, a1 = 0.f, a2 = 0.f, a3 = 0.f;
    const float4* W4 = (const float4*)W2;  // row k of [128][4] = one float4
#pragma unroll
    for (int j = 0; j < 4; j++) {
        float4 wr = W4[lane * 4 + j];
        a0 += tv[j] * wr.x; a1 += tv[j] * wr.y; a2 += tv[j] * wr.z; a3 += tv[j] * wr.w;
    }
    a0 = warp_sum(a0); a1 = warp_sum(a1); a2 = warp_sum(a2); a3 = warp_sum(a3);
    if (lane == 0) {
        out[(size_t)w * 4 + 0] = a0 + b2[0];
        out[(size_t)w * 4 + 1] = a1 + b2[1];
        out[(size_t)w * 4 + 2] = a2 + b2[2];
        out[(size_t)w * 4 + 3] = a3 + b2[3];
    }
}

// ---------------------------------------------------------------------------
// Host orchestration
// ---------------------------------------------------------------------------
extern "C" void kernel_launch(void* const* d_in, const int* in_sizes, int n_in,
                              void* d_out, int out_size) {
    const float* user_x      = (const float*)d_in[0];
    const float* post_x      = (const float*)d_in[1];
    const float* parent_feat = (const float*)d_in[2];
    const float* user_proj_W = (const float*)d_in[3];
    const float* user_proj_b = (const float*)d_in[4];
    const float* post_proj_W = (const float*)d_in[5];
    const float* post_proj_b = (const float*)d_in[6];
    const float* conv_W      = (const float*)d_in[7];
    const float* conv_b      = (const float*)d_in[8];
    const float* conv_g      = (const float*)d_in[9];
    const float* conv_beta   = (const float*)d_in[10];
    const float* uce_W       = (const float*)d_in[11];
    const float* uce_b       = (const float*)d_in[12];
    const float* Wself       = (const float*)d_in[13];
    const float* bself       = (const float*)d_in[14];
    const float* Wneigh      = (const float*)d_in[15];
    const float* bneigh      = (const float*)d_in[16];
    const float* ln_user_g   = (const float*)d_in[17];
    const float* ln_user_b   = (const float*)d_in[18];
    const float* ln_post_g   = (const float*)d_in[19];
    const float* ln_post_b   = (const float*)d_in[20];
    const float* cls_W1      = (const float*)d_in[21];
    const float* cls_b1      = (const float*)d_in[22];
    const float* cls_W2      = (const float*)d_in[23];
    const float* cls_b2      = (const float*)d_in[24];
    const int* publish_u     = (const int*)d_in[25];
    const int* publish_v     = (const int*)d_in[26];
    const int* comment_u     = (const int*)d_in[27];
    const int* comment_v     = (const int*)d_in[28];
    const int* ucu_u         = (const int*)d_in[29];
    const int* ucu_v         = (const int*)d_in[30];
    float* out = (float*)d_out;

    Scratch* S = nullptr;
    cudaGetSymbolAddress((void**)&S, gS);

    const int NBu = (Nu + 127) / 128;   // 391
    const int NBp = (Np + 127) / 128;   // 157

    // --- zero per-launch accumulators ---------------------------------------
    cudaMemsetAsync(S->cnt_pub_u, 0, sizeof(int) * (size_t)(4 * Nu + 2 * Np), 0);
    cudaMemsetAsync(S->nz, 0, sizeof(int) * 4, 0);
    cudaMemsetAsync(S->avgpost, 0, sizeof(float) * IN, 0);
    cudaMemsetAsync(S->ctx, 0, sizeof(float) * (size_t)Nu * H, 0);

    // --- counts / degrees ----------------------------------------------------
    {
        CJob c0 = {publish_u, Ep, S->cnt_pub_u};
        CJob c1 = {publish_v, Ep, S->cnt_pub_v};
        CJob c2 = {comment_u, Ec, S->cnt_com_u};
        CJob c3 = {comment_v, Ec, S->cnt_com_v};
        CJob c4 = {ucu_u, Eu, S->cnt_ucu_u};
        CJob c5 = {ucu_v, Eu, S->cnt_ucu_v};
        dim3 g((Ec + 255) / 256, 6);
        count6_kernel<<<g, 256>>>(c0, c1, c2, c3, c4, c5);
    }
    prep_user_kernel<<<(Nu + 255) / 256, 256>>>();
    prep_post_kernel<<<(Np + 255) / 256, 256>>>();

    // --- CSR build (scan + bin) ----------------------------------------------
    {
        ScanJobs sj;
        sj.j[0] = {S->cnt_pub_v, Np, S->off_pub_v, S->cur_pub_v};
        sj.j[1] = {S->cnt_com_v, Np, S->off_com_v, S->cur_com_v};
        sj.j[2] = {S->cnt_ucu_v, Nu, S->off_ucu_v, S->cur_ucu_v};
        sj.j[3] = {S->cnt_com_u, Nu, S->off_com_u, S->cur_com_u};
        sj.j[4] = {S->cnt_pub_u, Nu, S->off_pub_u, S->cur_pub_u};
        dim3 g1(SCAN_G, 5);
        scan1_kernel<<<g1, 256>>>(sj, S->blocksums);
        scan2_kernel<<<5, SCAN_G>>>(S->blocksums);
        scan3_kernel<<<g1, 256>>>(sj, S->blocksums);

        BJob b0 = {publish_v, publish_u, Ep, S->cur_pub_v, S->csr_pub_v};
        BJob b1 = {comment_v, comment_u, Ec, S->cur_com_v, S->csr_com_v};
        BJob b2 = {ucu_v, ucu_u, Eu, S->cur_ucu_v, S->csr_ucu_v};
        BJob b3 = {comment_u, comment_v, Ec, S->cur_com_u, S->csr_com_u};
        BJob b4 = {publish_u, publish_v, Ep, S->cur_pub_u, S->csr_pub_u};
        dim3 gb((Ec + 255) / 256, 5);
        bin5_kernel<<<gb, 256>>>(b0, b1, b2, b3, b4);
    }

    // --- constants -----------------------------------------------------------
    avgpost_kernel<<<512, 256>>>(post_x);
    cvec_kernel<<<1, 128>>>(conv_W, conv_b);

    // --- weight preprocessing (transpose + tf32) -----------------------------
    {
        WJobs js;
        js.j[0] = {user_proj_W, nullptr, S->Wt_up, 256};
        js.j[1] = {post_proj_W, nullptr, S->Wt_pp, 256};
        js.j[2] = {uce_W, nullptr, S->Wt_uce, 256};
        js.j[3] = {cls_W1, nullptr, S->Wt_cls, 128};
        js.j[4] = {conv_W, nullptr, S->Wt_conv, 64};   // conv_W[:64] rows only
        for (int l = 0; l < 2; l++) {
            js.j[5 + 5 * l + 0] = {Wself + (size_t)(l * 3 + 0) * HH, Wself + (size_t)(l * 3 + 1) * HH, S->Wt_ss[l], 128};
            js.j[5 + 5 * l + 1] = {Wneigh + (size_t)(l * 3 + 0) * HH, nullptr, S->Wt_n0[l], 128};
            js.j[5 + 5 * l + 2] = {Wneigh + (size_t)(l * 3 + 1) * HH, nullptr, S->Wt_n1[l], 128};
            js.j[5 + 5 * l + 3] = {Wself + (size_t)(l * 3 + 2) * HH, nullptr, S->Wt_s2[l], 128};
            js.j[5 + 5 * l + 4] = {Wneigh + (size_t)(l * 3 + 2) * HH, nullptr, S->Wt_n2[l], 128};
        }
        dim3 g(128, 15);
        wprep_kernel<<<g, 256>>>(js);
    }
    bcomb_kernel<<<1, 128>>>(bself, bneigh);

    Seg z = {nullptr, nullptr, nullptr, 0};
    GemmJob jz = {z, z, z, 0, nullptr, nullptr, nullptr, 0, 0};

    // --- input projections: 3 GEMM jobs in ONE launch ------------------------
    {
        GemmJob a = {{user_x, S->Wt_up, nullptr, 256}, z, z, 1,
                     user_proj_b, S->h_user, S->init_user, Nu, 1};
        GemmJob b = {{post_x, S->Wt_pp, nullptr, 256}, z, z, 1,
                     post_proj_b, S->h_post, S->init_post, Np, 1};
        GemmJob c = {{post_x, S->Wt_uce, nullptr, 256}, z, z, 1,
                     uce_b, S->post_enc, nullptr, Np, 2};
        gemm_multi<<<NBu + 2 * NBp, 256>>>(a, b, c, NBu, NBu + NBp);
    }

    // --- ctx: tensor-core conv edge-GEMM scatter + CSR gathers + blend --------
    conv_mma_kernel<<<(Eu + 127) / 128, 256>>>(parent_feat, S->Wt_conv, S->cvec, conv_g, conv_beta, ucu_u, S->ctx, Eu);
    ctx_blend_kernel<<<((size_t)Nu * 32 + 255) / 256, 256>>>();

    // --- SAGE layers ----------------------------------------------------------
    for (int l = 0; l < 2; l++) {
        gather_all_kernel<<<((size_t)(Np + Nu) * 32 + 255) / 256, 256>>>(S->h_user);

        // post_new and user_new in ONE launch (2 jobs)
        {
            GemmJob a = {{S->h_post, S->Wt_ss[l], nullptr, 128},
                         {S->agg_pub, S->Wt_n0[l], S->inv_pub_v, 128},
                         {S->agg_com, S->Wt_n1[l], S->inv_com_v, 128}, 3,
                         S->b_post[l], S->post_new, nullptr, Np, 0};
            GemmJob b = {{S->h_user, S->Wt_s2[l], nullptr, 128},
                         {S->agg_ucu, S->Wt_n2[l], S->inv_ucu_v, 128}, z, 2,
                         S->b_user[l], S->user_new, nullptr, Nu, 0};
            gemm_multi<<<NBp + NBu, 256>>>(a, b, jz, NBp, NBp + NBu);
        }

        cudaMemsetAsync(S->gm_user, 0, sizeof(float) * 2 * H, 0);  // gm_user + gm_post
        {
            dim3 g(512, 2);
            colsum2_kernel<<<g, 256>>>();
        }
        if (l == 0)
            fixln_all_kernel<true><<<((size_t)(Nu + Np) * 32 + 255) / 256, 256>>>(ln_user_g, ln_user_b, ln_post_g, ln_post_b);
        else
            fixln_all_kernel<false><<<((size_t)(Nu + Np) * 32 + 255) / 256, 256>>>(ln_user_g, ln_user_b, ln_post_g, ln_post_b);
    }

    // --- classifier -----------------------------------------------------------
    {
        GemmJob a = {{S->h_user, S->Wt_cls, nullptr, 128}, z, z, 1,
                     cls_b1, S->user_new, nullptr, Nu, 1};
        gemm_multi<<<NBu, 256>>>(a, jz, jz, NBu, NBu);
    }
    cls2_kernel<<<((size_t)Nu * 32 + 255) / 256, 256>>>(S->user_new, cls_W2, cls_b2, out, Nu);
}